// round 2
// baseline (speedup 1.0000x reference)
#include <cuda_runtime.h>
#include <math.h>

#define BB 2
#define SS 2048
#define EE 1024
#define HH 32
#define KK 8
#define DD 128
#define BSZ (BB*SS)     // 4096 tokens
#define BKH (BB*KK)     // 16 head-slots

// ---------------- scratch (static device globals; no allocation) ----------------
static __device__ float g_hw[BSZ*KK];        // head weights per token-slot
static __device__ float g_probs[BSZ*HH];     // soft probs per token (for aux loss)
static __device__ float g_ent[BSZ];          // per-token entropy
static __device__ int   g_primary[BSZ];      // primary head per token
static __device__ int   g_bcnt[HH];          // bucket counts
static __device__ int   g_bucket[HH*BSZ];    // token-slot codes per head
static __device__ float g_q[(size_t)BKH*SS*DD];
static __device__ float g_k[(size_t)BKH*SS*DD];
static __device__ float g_v[(size_t)BKH*SS*DD];
static __device__ float g_o[(size_t)BSZ*KK*DD];   // [b,s,k,d] layout (= A of out-proj)

// ---------------- kernel 0: zero bucket counters ----------------
__global__ void zero_kernel() {
    if (threadIdx.x < HH) g_bcnt[threadIdx.x] = 0;
}

// ---------------- kernel 1: router (one block per token) ----------------
__global__ __launch_bounds__(256) void router_kernel(const float* __restrict__ x,
                                                     const float* __restrict__ Wr) {
    const int token = blockIdx.x;
    __shared__ float xs[EE];
    __shared__ float part[8][HH];
    __shared__ float s_topv[KK];
    __shared__ int   s_topi[KK];
    const int tid = threadIdx.x;

    // stage x row in smem
    const float4* xv = (const float4*)(x + (size_t)token * EE);
    float4* xsv = (float4*)xs;
    for (int i = tid; i < EE/4; i += 256) xsv[i] = xv[i];
    __syncthreads();

    const int warp = tid >> 5, lane = tid & 31;
    float acc = 0.f;
    const int e0 = warp * 128;
    #pragma unroll 4
    for (int e = 0; e < 128; e++)
        acc = fmaf(xs[e0 + e], Wr[(size_t)(e0 + e) * HH + lane], acc);
    part[warp][lane] = acc;
    __syncthreads();

    if (warp == 0) {
        float logit = 0.f;
        #pragma unroll
        for (int w = 0; w < 8; w++) logit += part[w][lane];

        // softmax over 32 heads
        float m = logit;
        #pragma unroll
        for (int o = 16; o; o >>= 1) m = fmaxf(m, __shfl_xor_sync(0xffffffffu, m, o));
        float ex = expf(logit - m);
        float sum = ex;
        #pragma unroll
        for (int o = 16; o; o >>= 1) sum += __shfl_xor_sync(0xffffffffu, sum, o);
        float prob = ex / sum;
        g_probs[(size_t)token * HH + lane] = prob;
        float et = -prob * logf(prob + 1e-8f);
        #pragma unroll
        for (int o = 16; o; o >>= 1) et += __shfl_xor_sync(0xffffffffu, et, o);
        if (lane == 0) g_ent[token] = et;

        // top-8: iterative argmax, ties -> lower index (matches jax.lax.top_k)
        float cur = logit;
        for (int j = 0; j < KK; j++) {
            float bv = cur; int bi = lane;
            #pragma unroll
            for (int o = 16; o; o >>= 1) {
                float ov = __shfl_xor_sync(0xffffffffu, bv, o);
                int   oi = __shfl_xor_sync(0xffffffffu, bi, o);
                if (ov > bv || (ov == bv && oi < bi)) { bv = ov; bi = oi; }
            }
            if (lane == 0) { s_topv[j] = bv; s_topi[j] = bi; }
            if (lane == bi) cur = -INFINITY;
        }
        __syncwarp();

        if (lane < KK) {
            float tv = s_topv[lane];
            float e2 = expf(tv - s_topv[0]);
            float s2 = e2;
            #pragma unroll
            for (int o = 4; o; o >>= 1) s2 += __shfl_xor_sync(0x000000ffu, s2, o, 8);
            int hsel = s_topi[lane];
            g_hw[token * KK + lane] = e2 / s2;
            int pos = atomicAdd(&g_bcnt[hsel], 1);
            g_bucket[hsel * BSZ + pos] = token * KK + lane;  // code = token*8 + slot
        }
        if (lane == 0) g_primary[token] = s_topi[0];
    }
}

// ---------------- kernel 2: bucketed gather projection (q/k/v) ----------------
// grid: (BSZ/64, HH, 3), block 128. Tile: 64 tokens x 128 dims, K-chunks of 16.
__global__ __launch_bounds__(128) void proj_kernel(const float* __restrict__ x,
                                                   const float* __restrict__ Wq,
                                                   const float* __restrict__ Wk,
                                                   const float* __restrict__ Wv) {
    const int h = blockIdx.y;
    const int cnt = g_bcnt[h];
    const int t0 = blockIdx.x * 64;
    if (t0 >= cnt) return;
    const int mat = blockIdx.z;
    const float* W = (mat == 0 ? Wq : mat == 1 ? Wk : Wv) + h * DD;
    float* dst = (mat == 0 ? g_q : mat == 1 ? g_k : g_v);

    const int tid = threadIdx.x;
    __shared__ int codes[64];
    __shared__ float Xs[16][64];     // [e][token] transposed
    __shared__ float Ws[16][128];    // [e][dim]

    if (tid < 64) {
        int ii = t0 + tid;
        codes[tid] = (ii < cnt) ? g_bucket[h * BSZ + ii] : -1;
    }
    __syncthreads();

    const int ty = tid >> 4;   // 0..7  -> rows {ty + 8i}
    const int tx = tid & 15;   // 0..15 -> dims {tx + 16j}
    const int lt = tid >> 1;   // loader token 0..63
    const int eb = (tid & 1) * 8;
    int mycode = codes[lt];
    const float* xrow = x + (size_t)(mycode >= 0 ? (mycode >> 3) : 0) * EE + eb;

    float acc[8][8];
    #pragma unroll
    for (int i = 0; i < 8; i++)
        #pragma unroll
        for (int j = 0; j < 8; j++) acc[i][j] = 0.f;

    for (int ec = 0; ec < EE; ec += 16) {
        __syncthreads();
        float4 a0 = *(const float4*)(xrow + ec);
        float4 a1 = *(const float4*)(xrow + ec + 4);
        Xs[eb+0][lt] = a0.x; Xs[eb+1][lt] = a0.y; Xs[eb+2][lt] = a0.z; Xs[eb+3][lt] = a0.w;
        Xs[eb+4][lt] = a1.x; Xs[eb+5][lt] = a1.y; Xs[eb+6][lt] = a1.z; Xs[eb+7][lt] = a1.w;
        #pragma unroll
        for (int r = 0; r < 4; r++) {
            int e = (tid >> 5) + 4 * r;
            int d = (tid & 31) << 2;
            *(float4*)&Ws[e][d] = *(const float4*)(W + (size_t)(ec + e) * (HH * DD) + d);
        }
        __syncthreads();
        #pragma unroll
        for (int e = 0; e < 16; e++) {
            float a[8], bv[8];
            #pragma unroll
            for (int i = 0; i < 8; i++) a[i] = Xs[e][ty + 8 * i];
            #pragma unroll
            for (int j = 0; j < 8; j++) bv[j] = Ws[e][tx + 16 * j];
            #pragma unroll
            for (int i = 0; i < 8; i++)
                #pragma unroll
                for (int j = 0; j < 8; j++)
                    acc[i][j] = fmaf(a[i], bv[j], acc[i][j]);
        }
    }

    #pragma unroll
    for (int i = 0; i < 8; i++) {
        int code = codes[ty + 8 * i];
        if (code < 0) continue;
        int token = code >> 3, slot = code & 7;
        int b = token >> 11, s = token & (SS - 1);
        size_t basei = ((size_t)((b * KK + slot) * SS + s)) * DD;
        #pragma unroll
        for (int j = 0; j < 8; j++)
            dst[basei + tx + 16 * j] = acc[i][j];
    }
}

// ---------------- kernel 3: RoPE on q and k ----------------
__global__ void rope_kernel() {
    int idx = blockIdx.x * blockDim.x + threadIdx.x;   // pair index
    const int total = BKH * SS * (DD / 2);
    if (idx >= total) return;
    int d = idx & 63;
    int rest = idx >> 6;               // bk*S + s
    int s = rest & (SS - 1);
    float inv = expf(-(float)d * (9.210340371976184f / 64.f));  // 10000^(-d/64)
    float fr = (float)s * inv;
    float sn, cs;
    sincosf(fr, &sn, &cs);
    size_t i0 = ((size_t)rest << 7) + d;
    float q1 = g_q[i0], q2 = g_q[i0 + 64];
    g_q[i0]      = q1 * cs - q2 * sn;
    g_q[i0 + 64] = q2 * cs + q1 * sn;
    float k1 = g_k[i0], k2 = g_k[i0 + 64];
    g_k[i0]      = k1 * cs - k2 * sn;
    g_k[i0 + 64] = k2 * cs + k1 * sn;
}

// ---------------- kernel 4: causal flash attention ----------------
// grid: (16 head-slots, 64 q-tiles of 32 rows), block 128
__global__ __launch_bounds__(128) void attn_kernel() {
    const int bk = blockIdx.x;
    const int qt = blockIdx.y;
    const int qbase = qt * 32;
    const int b = bk >> 3, kslot = bk & 7;
    const int tid = threadIdx.x;

    __shared__ float Qs[32][132];
    __shared__ float KVs[32][132];
    __shared__ float Ps[32][33];
    __shared__ float s_m[32], s_l[32], s_alpha[32];

    const float* Qp = g_q + (size_t)bk * SS * DD;
    const float* Kp = g_k + (size_t)bk * SS * DD;
    const float* Vp = g_v + (size_t)bk * SS * DD;

    for (int i = tid; i < 32 * 32; i += 128) {
        int r = i >> 5, c4 = (i & 31) << 2;
        *(float4*)&Qs[r][c4] = *(const float4*)(Qp + (size_t)(qbase + r) * DD + c4);
    }
    if (tid < 32) { s_m[tid] = -INFINITY; s_l[tid] = 0.f; }

    const int ry = tid >> 3;   // S-stage: rows {ry, ry+16}
    const int cx = tid & 7;    //           cols {cx + 8j}
    const int rw = tid >> 4;   // O-stage: rows {rw + 8i}
    const int dx = tid & 15;   //           dims {dx + 16j}

    float o[4][8];
    #pragma unroll
    for (int i = 0; i < 4; i++)
        #pragma unroll
        for (int j = 0; j < 8; j++) o[i][j] = 0.f;

    const float scale = 0.08838834764831843f;  // 1/sqrt(128)

    for (int kt = 0; kt <= qt; kt++) {
        const int kb = kt * 32;
        __syncthreads();
        for (int i = tid; i < 32 * 32; i += 128) {
            int r = i >> 5, c4 = (i & 31) << 2;
            *(float4*)&KVs[r][c4] = *(const float4*)(Kp + (size_t)(kb + r) * DD + c4);
        }
        __syncthreads();

        float sv[2][4];
        #pragma unroll
        for (int i = 0; i < 2; i++)
            #pragma unroll
            for (int j = 0; j < 4; j++) sv[i][j] = 0.f;
        #pragma unroll 4
        for (int d = 0; d < DD; d++) {
            float a0 = Qs[ry][d];
            float a1 = Qs[ry + 16][d];
            #pragma unroll
            for (int j = 0; j < 4; j++) {
                float kv = KVs[cx + 8 * j][d];
                sv[0][j] = fmaf(a0, kv, sv[0][j]);
                sv[1][j] = fmaf(a1, kv, sv[1][j]);
            }
        }
        #pragma unroll
        for (int i = 0; i < 2; i++) {
            int r = ry + 16 * i;
            int qrow = qbase + r;
            float mrow = -INFINITY;
            #pragma unroll
            for (int j = 0; j < 4; j++) {
                int kcol = kb + cx + 8 * j;
                sv[i][j] = (kcol <= qrow) ? sv[i][j] * scale : -INFINITY;
                mrow = fmaxf(mrow, sv[i][j]);
            }
            #pragma unroll
            for (int off = 4; off; off >>= 1)
                mrow = fmaxf(mrow, __shfl_xor_sync(0xffffffffu, mrow, off));
            float mprev = s_m[r];
            float mnew = fmaxf(mprev, mrow);
            float rsum = 0.f;
            #pragma unroll
            for (int j = 0; j < 4; j++) {
                float p = expf(sv[i][j] - mnew);
                Ps[r][cx + 8 * j] = p;
                rsum += p;
            }
            #pragma unroll
            for (int off = 4; off; off >>= 1)
                rsum += __shfl_xor_sync(0xffffffffu, rsum, off);
            if (cx == 0) {
                float alpha = expf(mprev - mnew);
                s_alpha[r] = alpha;
                s_m[r] = mnew;
                s_l[r] = s_l[r] * alpha + rsum;
            }
        }
        __syncthreads();
        for (int i = tid; i < 32 * 32; i += 128) {
            int r = i >> 5, c4 = (i & 31) << 2;
            *(float4*)&KVs[r][c4] = *(const float4*)(Vp + (size_t)(kb + r) * DD + c4);
        }
        __syncthreads();

        float al[4];
        #pragma unroll
        for (int i = 0; i < 4; i++) al[i] = s_alpha[rw + 8 * i];
        #pragma unroll
        for (int i = 0; i < 4; i++)
            #pragma unroll
            for (int j = 0; j < 8; j++) o[i][j] *= al[i];
        #pragma unroll 2
        for (int c = 0; c < 32; c++) {
            float p[4];
            #pragma unroll
            for (int i = 0; i < 4; i++) p[i] = Ps[rw + 8 * i][c];
            #pragma unroll
            for (int j = 0; j < 8; j++) {
                float v = KVs[c][dx + 16 * j];
                #pragma unroll
                for (int i = 0; i < 4; i++) o[i][j] = fmaf(p[i], v, o[i][j]);
            }
        }
    }
    __syncthreads();
    #pragma unroll
    for (int i = 0; i < 4; i++) {
        int r = rw + 8 * i;
        int token = b * SS + qbase + r;
        float w = g_hw[token * KK + kslot] / s_l[r];
        size_t basei = ((size_t)token * KK + kslot) * DD;
        #pragma unroll
        for (int j = 0; j < 8; j++)
            g_o[basei + dx + 16 * j] = o[i][j] * w;
    }
}

// ---------------- kernel 5: output projection ----------------
// C[4096,1024] = g_o[4096,1024] @ Wo[1024,1024]; tile 64x128, block 128
__global__ __launch_bounds__(128) void outproj_kernel(const float* __restrict__ Wo,
                                                      float* __restrict__ out) {
    const int rbase = blockIdx.x * 64;
    const int cbase = blockIdx.y * 128;
    const int tid = threadIdx.x;
    __shared__ float As[16][64];
    __shared__ float Ws[16][128];
    const int ty = tid >> 4, tx = tid & 15;
    const int lt = tid >> 1;
    const int eb = (tid & 1) * 8;
    const float* arow = g_o + (size_t)(rbase + lt) * EE + eb;

    float acc[8][8];
    #pragma unroll
    for (int i = 0; i < 8; i++)
        #pragma unroll
        for (int j = 0; j < 8; j++) acc[i][j] = 0.f;

    for (int ec = 0; ec < EE; ec += 16) {
        __syncthreads();
        float4 a0 = *(const float4*)(arow + ec);
        float4 a1 = *(const float4*)(arow + ec + 4);
        As[eb+0][lt] = a0.x; As[eb+1][lt] = a0.y; As[eb+2][lt] = a0.z; As[eb+3][lt] = a0.w;
        As[eb+4][lt] = a1.x; As[eb+5][lt] = a1.y; As[eb+6][lt] = a1.z; As[eb+7][lt] = a1.w;
        #pragma unroll
        for (int r = 0; r < 4; r++) {
            int e = (tid >> 5) + 4 * r;
            int d = (tid & 31) << 2;
            *(float4*)&Ws[e][d] = *(const float4*)(Wo + (size_t)(ec + e) * EE + cbase + d);
        }
        __syncthreads();
        #pragma unroll
        for (int e = 0; e < 16; e++) {
            float a[8], bv[8];
            #pragma unroll
            for (int i = 0; i < 8; i++) a[i] = As[e][ty + 8 * i];
            #pragma unroll
            for (int j = 0; j < 8; j++) bv[j] = Ws[e][tx + 16 * j];
            #pragma unroll
            for (int i = 0; i < 8; i++)
                #pragma unroll
                for (int j = 0; j < 8; j++)
                    acc[i][j] = fmaf(a[i], bv[j], acc[i][j]);
        }
    }
    #pragma unroll
    for (int i = 0; i < 8; i++) {
        size_t row = rbase + ty + 8 * i;
        #pragma unroll
        for (int j = 0; j < 8; j++)
            out[row * EE + cbase + tx + 16 * j] = acc[i][j];
    }
}

// ---------------- kernel 6: aux loss + head_counts tail (deterministic) ----------------
__global__ void finalize_kernel(float* __restrict__ out, int out_size) {
    __shared__ float s_bal[BB * HH];
    __shared__ float s_ent[256];
    const int tid = threadIdx.x;
    if (tid < BB * HH) {
        int b = tid / HH, h = tid % HH;
        float psum = 0.f, fcnt = 0.f;
        for (int s = 0; s < SS; s++) {
            psum += g_probs[(size_t)(b * SS + s) * HH + h];
            fcnt += (g_primary[b * SS + s] == h) ? 1.f : 0.f;
        }
        s_bal[tid] = (fcnt / SS) * (psum / SS);
    }
    float e = 0.f;
    for (int i = tid; i < BSZ; i += 256) e += g_ent[i];
    s_ent[tid] = e;
    __syncthreads();
    const int base = BSZ * EE;
    if (tid == 0 && out_size > base) {
        float bal = 0.f;
        for (int i = 0; i < BB * HH; i++) bal += s_bal[i];
        bal = (float)HH * (bal / BB);
        float ent = 0.f;
        for (int i = 0; i < 256; i++) ent += s_ent[i];
        ent /= (float)BSZ;
        out[out_size - 1] = bal - 0.01f * ent;
    }
    if (out_size > base) {
        for (int i = base + tid; i < out_size - 1; i += 256) out[i] = 0.f;
    }
}

// ---------------- launcher ----------------
extern "C" void kernel_launch(void* const* d_in, const int* in_sizes, int n_in,
                              void* d_out, int out_size) {
    // Inputs are in metadata.txt order (= setup_inputs dict order):
    //   0: x [B,S,E]   1: Wq [E,H*D]   2: Wk   3: Wv   4: Wr [E,H]   5: Wo [K*D,E]
    // NOTE: x and Wq/Wk/Wv have IDENTICAL element counts (4,194,304) — size-based
    // matching is ambiguous, so use positions; verify the two uniquely-sized ones.
    const float* x  = (const float*)d_in[0];
    const float* Wq = (const float*)d_in[1];
    const float* Wk = (const float*)d_in[2];
    const float* Wv = (const float*)d_in[3];
    const float* Wr = (const float*)d_in[4];
    const float* Wo = (const float*)d_in[5];
    // fallback: locate Wr / Wo by unique sizes if order differs
    for (int i = 0; i < n_in; i++) {
        if (in_sizes[i] == EE * HH)      Wr = (const float*)d_in[i];
        if (in_sizes[i] == KK * DD * EE) Wo = (const float*)d_in[i];
    }
    float* out = (float*)d_out;

    zero_kernel<<<1, 32>>>();
    router_kernel<<<BSZ, 256>>>(x, Wr);
    proj_kernel<<<dim3(BSZ / 64, HH, 3), 128>>>(x, Wq, Wk, Wv);
    rope_kernel<<<(BKH * SS * (DD / 2) + 255) / 256, 256>>>();
    attn_kernel<<<dim3(BKH, SS / 32), 128>>>();
    outproj_kernel<<<dim3(BSZ / 64, EE / 128), 128>>>(Wo, out);
    finalize_kernel<<<1, 256>>>(out, out_size);
}

// round 3
// speedup vs baseline: 2.3973x; 2.3973x over previous
#include <cuda_runtime.h>
#include <math.h>
#include <stdint.h>

#define BB 2
#define SS 2048
#define EE 1024
#define HH 32
#define KK 8
#define DD 128
#define BSZ (BB*SS)     // 4096 tokens
#define BKH (BB*KK)     // 16 head-slots

// ---------------- scratch ----------------
static __device__ float g_hw[BSZ*KK];
static __device__ float g_probs[BSZ*HH];
static __device__ float g_ent[BSZ];
static __device__ int   g_primary[BSZ];
static __device__ int   g_bcnt[HH];
static __device__ int   g_bucket[HH*BSZ];
static __device__ float g_q[(size_t)BKH*SS*DD];
static __device__ float g_k[(size_t)BKH*SS*DD];
static __device__ float g_v[(size_t)BKH*SS*DD];
static __device__ float g_o[(size_t)BSZ*KK*DD];

// ---------------- tf32 helpers ----------------
__device__ __forceinline__ uint32_t f2tf(float f) {
    uint32_t u;
    asm("cvt.rna.tf32.f32 %0, %1;" : "=r"(u) : "f"(f));
    return u;
}
__device__ __forceinline__ void mma8(float* cc, const uint32_t* a, uint32_t b0, uint32_t b1) {
    asm volatile(
        "mma.sync.aligned.m16n8k8.row.col.f32.tf32.tf32.f32 "
        "{%0,%1,%2,%3},{%4,%5,%6,%7},{%8,%9},{%0,%1,%2,%3};\n"
        : "+f"(cc[0]), "+f"(cc[1]), "+f"(cc[2]), "+f"(cc[3])
        : "r"(a[0]), "r"(a[1]), "r"(a[2]), "r"(a[3]), "r"(b0), "r"(b1));
}

// ---------------- kernel 0 ----------------
__global__ void zero_kernel() {
    if (threadIdx.x < HH) g_bcnt[threadIdx.x] = 0;
}

// ---------------- kernel 1: router (exact fp32) ----------------
__global__ __launch_bounds__(256) void router_kernel(const float* __restrict__ x,
                                                     const float* __restrict__ Wr) {
    const int token = blockIdx.x;
    __shared__ float xs[EE];
    __shared__ float part[8][HH];
    __shared__ float s_topv[KK];
    __shared__ int   s_topi[KK];
    const int tid = threadIdx.x;

    const float4* xv = (const float4*)(x + (size_t)token * EE);
    float4* xsv = (float4*)xs;
    for (int i = tid; i < EE/4; i += 256) xsv[i] = xv[i];
    __syncthreads();

    const int warp = tid >> 5, lane = tid & 31;
    float acc = 0.f;
    const int e0 = warp * 128;
    #pragma unroll 4
    for (int e = 0; e < 128; e++)
        acc = fmaf(xs[e0 + e], Wr[(size_t)(e0 + e) * HH + lane], acc);
    part[warp][lane] = acc;
    __syncthreads();

    if (warp == 0) {
        float logit = 0.f;
        #pragma unroll
        for (int w = 0; w < 8; w++) logit += part[w][lane];

        float m = logit;
        #pragma unroll
        for (int o = 16; o; o >>= 1) m = fmaxf(m, __shfl_xor_sync(0xffffffffu, m, o));
        float ex = expf(logit - m);
        float sum = ex;
        #pragma unroll
        for (int o = 16; o; o >>= 1) sum += __shfl_xor_sync(0xffffffffu, sum, o);
        float prob = ex / sum;
        g_probs[(size_t)token * HH + lane] = prob;
        float et = -prob * logf(prob + 1e-8f);
        #pragma unroll
        for (int o = 16; o; o >>= 1) et += __shfl_xor_sync(0xffffffffu, et, o);
        if (lane == 0) g_ent[token] = et;

        float cur = logit;
        for (int j = 0; j < KK; j++) {
            float bv = cur; int bi = lane;
            #pragma unroll
            for (int o = 16; o; o >>= 1) {
                float ov = __shfl_xor_sync(0xffffffffu, bv, o);
                int   oi = __shfl_xor_sync(0xffffffffu, bi, o);
                if (ov > bv || (ov == bv && oi < bi)) { bv = ov; bi = oi; }
            }
            if (lane == 0) { s_topv[j] = bv; s_topi[j] = bi; }
            if (lane == bi) cur = -INFINITY;
        }
        __syncwarp();

        if (lane < KK) {
            float tv = s_topv[lane];
            float e2 = expf(tv - s_topv[0]);
            float s2 = e2;
            #pragma unroll
            for (int o = 4; o; o >>= 1) s2 += __shfl_xor_sync(0x000000ffu, s2, o, 8);
            int hsel = s_topi[lane];
            g_hw[token * KK + lane] = e2 / s2;
            int pos = atomicAdd(&g_bcnt[hsel], 1);
            g_bucket[hsel * BSZ + pos] = token * KK + lane;
        }
        if (lane == 0) g_primary[token] = s_topi[0];
    }
}

// ---------------- kernel 2: bucketed gather projection with tf32 MMA ----------------
// Block 256 thr = 8 warps, tile 128 tokens x 128 dims. Warp tile 32x64.
__global__ __launch_bounds__(256) void proj_mma_kernel(const float* __restrict__ x,
                                                       const float* __restrict__ Wq,
                                                       const float* __restrict__ Wk,
                                                       const float* __restrict__ Wv) {
    const int h = blockIdx.y;
    const int cnt = g_bcnt[h];
    const int t0 = blockIdx.x * 128;
    if (t0 >= cnt) return;
    const int mat = blockIdx.z;
    const float* W = (mat == 0 ? Wq : mat == 1 ? Wk : Wv) + h * DD;
    float* dst = (mat == 0 ? g_q : mat == 1 ? g_k : g_v);

    __shared__ int codes[128];
    __shared__ uint32_t Xs[32][136];   // [k][row], tf32 bits
    __shared__ uint32_t Ws[32][132];   // [k][n],  tf32 bits

    const int tid = threadIdx.x;
    const int lane = tid & 31, warp = tid >> 5;
    const int g = lane >> 2, c = lane & 3;
    const int wr = (warp >> 1) * 32;       // warp row base (0,32,64,96)
    const int wc = (warp & 1) * 64;        // warp col base (0,64)

    if (tid < 128) {
        int ii = t0 + tid;
        codes[tid] = (ii < cnt) ? g_bucket[h * BSZ + ii] : -1;
    }
    __syncthreads();

    const int myrow = tid >> 1;
    const int koff = (tid & 1) * 16;
    int mycode = codes[myrow];
    const float* xrow = x + (size_t)(mycode >= 0 ? (mycode >> 3) : 0) * EE + koff;

    float acc[2][8][4];
    #pragma unroll
    for (int mt = 0; mt < 2; mt++)
        #pragma unroll
        for (int nt = 0; nt < 8; nt++)
            #pragma unroll
            for (int q = 0; q < 4; q++) acc[mt][nt][q] = 0.f;

    for (int ec = 0; ec < EE; ec += 32) {
        __syncthreads();
        // stage X (gathered, transposed to k-major)
        #pragma unroll
        for (int j = 0; j < 4; j++) {
            float4 v = *(const float4*)(xrow + ec + 4 * j);
            Xs[koff + 4*j + 0][myrow] = f2tf(v.x);
            Xs[koff + 4*j + 1][myrow] = f2tf(v.y);
            Xs[koff + 4*j + 2][myrow] = f2tf(v.z);
            Xs[koff + 4*j + 3][myrow] = f2tf(v.w);
        }
        // stage W
        #pragma unroll
        for (int r = 0; r < 4; r++) {
            int i = tid + 256 * r;
            int k = i >> 5, n4 = (i & 31) * 4;
            float4 v = *(const float4*)(W + (size_t)(ec + k) * (HH * DD) + n4);
            uint4 u = { f2tf(v.x), f2tf(v.y), f2tf(v.z), f2tf(v.w) };
            *(uint4*)&Ws[k][n4] = u;
        }
        __syncthreads();

        #pragma unroll
        for (int ks = 0; ks < 4; ks++) {
            uint32_t a[2][4];
            #pragma unroll
            for (int mt = 0; mt < 2; mt++) {
                int row = wr + mt * 16;
                a[mt][0] = Xs[ks*8 + c    ][row + g];
                a[mt][1] = Xs[ks*8 + c    ][row + g + 8];
                a[mt][2] = Xs[ks*8 + c + 4][row + g];
                a[mt][3] = Xs[ks*8 + c + 4][row + g + 8];
            }
            #pragma unroll
            for (int nt = 0; nt < 8; nt++) {
                uint32_t b0 = Ws[ks*8 + c    ][wc + nt*8 + g];
                uint32_t b1 = Ws[ks*8 + c + 4][wc + nt*8 + g];
                mma8(acc[0][nt], a[0], b0, b1);
                mma8(acc[1][nt], a[1], b0, b1);
            }
        }
    }

    // epilogue: scatter rows by code
    #pragma unroll
    for (int mt = 0; mt < 2; mt++) {
        int r0 = wr + mt * 16 + g;
        int r1 = r0 + 8;
        int code0 = codes[r0], code1 = codes[r1];
        size_t base0 = 0, base1 = 0;
        if (code0 >= 0) {
            int token = code0 >> 3, slot = code0 & 7;
            base0 = ((size_t)(((token >> 11) * KK + slot) * SS + (token & (SS-1)))) * DD;
        }
        if (code1 >= 0) {
            int token = code1 >> 3, slot = code1 & 7;
            base1 = ((size_t)(((token >> 11) * KK + slot) * SS + (token & (SS-1)))) * DD;
        }
        #pragma unroll
        for (int nt = 0; nt < 8; nt++) {
            int col = wc + nt * 8 + 2 * c;
            if (code0 >= 0) { float2 v = { acc[mt][nt][0], acc[mt][nt][1] }; *(float2*)&dst[base0 + col] = v; }
            if (code1 >= 0) { float2 v = { acc[mt][nt][2], acc[mt][nt][3] }; *(float2*)&dst[base1 + col] = v; }
        }
    }
}

// ---------------- kernel 3: RoPE ----------------
__global__ void rope_kernel() {
    int idx = blockIdx.x * blockDim.x + threadIdx.x;
    const int total = BKH * SS * (DD / 2);
    if (idx >= total) return;
    int d = idx & 63;
    int rest = idx >> 6;
    int s = rest & (SS - 1);
    float inv = expf(-(float)d * (9.210340371976184f / 64.f));
    float fr = (float)s * inv;
    float sn, cs;
    sincosf(fr, &sn, &cs);
    size_t i0 = ((size_t)rest << 7) + d;
    float q1 = g_q[i0], q2 = g_q[i0 + 64];
    g_q[i0]      = q1 * cs - q2 * sn;
    g_q[i0 + 64] = q2 * cs + q1 * sn;
    float k1 = g_k[i0], k2 = g_k[i0 + 64];
    g_k[i0]      = k1 * cs - k2 * sn;
    g_k[i0 + 64] = k2 * cs + k1 * sn;
}

// ---------------- kernel 4: flash attention with tf32 MMA ----------------
// grid (16 slots, 32 q-tiles), block 128 = 4 warps. q-tile 64 rows (warp=16), kv-tile 64.
__global__ __launch_bounds__(128, 2) void attn_mma_kernel() {
    const int bk = blockIdx.x;
    const int qt = gridDim.y - 1 - blockIdx.y;     // big tiles first
    const int qbase = qt * 64;
    const int b = bk >> 3, kslot = bk & 7;
    const int tid = threadIdx.x;
    const int lane = tid & 31, warp = tid >> 5;
    const int g = lane >> 2, c = lane & 3;

    __shared__ uint32_t KVs[64][132];

    const float* Qp = g_q + (size_t)bk * SS * DD;
    const float* Kp = g_k + (size_t)bk * SS * DD;
    const float* Vp = g_v + (size_t)bk * SS * DD;

    const float scale = 0.08838834764831843f;  // 1/sqrt(128)

    // Q fragments in registers, pre-scaled
    const int r0 = qbase + warp * 16 + g;   // global q row
    const int r1 = r0 + 8;
    uint32_t qf[16][4];
    {
        const float* q0 = Qp + (size_t)r0 * DD;
        const float* q1 = Qp + (size_t)r1 * DD;
        #pragma unroll
        for (int ks = 0; ks < 16; ks++) {
            qf[ks][0] = f2tf(q0[8*ks + c    ] * scale);
            qf[ks][1] = f2tf(q1[8*ks + c    ] * scale);
            qf[ks][2] = f2tf(q0[8*ks + c + 4] * scale);
            qf[ks][3] = f2tf(q1[8*ks + c + 4] * scale);
        }
    }

    float o[16][4];
    #pragma unroll
    for (int nt = 0; nt < 16; nt++)
        #pragma unroll
        for (int q = 0; q < 4; q++) o[nt][q] = 0.f;
    float m0 = -INFINITY, m1 = -INFINITY, l0 = 0.f, l1 = 0.f;

    const int lrow = tid >> 1;
    const int coff = (tid & 1) * 64;

    for (int kt = 0; kt <= qt; kt++) {
        const int kb = kt * 64;
        __syncthreads();
        // load K tile (tf32) : KVs[kvrow][d]
        {
            const float* kp = Kp + (size_t)(kb + lrow) * DD + coff;
            #pragma unroll
            for (int j = 0; j < 16; j++) {
                float4 v = *(const float4*)(kp + 4 * j);
                uint4 u = { f2tf(v.x), f2tf(v.y), f2tf(v.z), f2tf(v.w) };
                *(uint4*)&KVs[lrow][coff + 4*j] = u;
            }
        }
        __syncthreads();

        // S = Q K^T
        float s[8][4];
        #pragma unroll
        for (int nt = 0; nt < 8; nt++)
            #pragma unroll
            for (int q = 0; q < 4; q++) s[nt][q] = 0.f;
        #pragma unroll
        for (int ks = 0; ks < 16; ks++) {
            #pragma unroll
            for (int nt = 0; nt < 8; nt++) {
                uint32_t b0 = KVs[nt*8 + g][8*ks + c    ];
                uint32_t b1 = KVs[nt*8 + g][8*ks + c + 4];
                mma8(s[nt], qf[ks], b0, b1);
            }
        }

        // causal mask on diagonal tile
        if (kt == qt) {
            #pragma unroll
            for (int nt = 0; nt < 8; nt++) {
                int col = kb + nt * 8 + 2 * c;
                if (col     > r0) s[nt][0] = -INFINITY;
                if (col + 1 > r0) s[nt][1] = -INFINITY;
                if (col     > r1) s[nt][2] = -INFINITY;
                if (col + 1 > r1) s[nt][3] = -INFINITY;
            }
        }

        // online softmax (rows r0 / r1, quad-shared)
        float mx0 = -INFINITY, mx1 = -INFINITY;
        #pragma unroll
        for (int nt = 0; nt < 8; nt++) {
            mx0 = fmaxf(mx0, fmaxf(s[nt][0], s[nt][1]));
            mx1 = fmaxf(mx1, fmaxf(s[nt][2], s[nt][3]));
        }
        #pragma unroll
        for (int off = 1; off <= 2; off <<= 1) {
            mx0 = fmaxf(mx0, __shfl_xor_sync(0xffffffffu, mx0, off));
            mx1 = fmaxf(mx1, __shfl_xor_sync(0xffffffffu, mx1, off));
        }
        float mn0 = fmaxf(m0, mx0), mn1 = fmaxf(m1, mx1);
        float al0 = __expf(m0 - mn0), al1 = __expf(m1 - mn1);
        m0 = mn0; m1 = mn1;
        float rs0 = 0.f, rs1 = 0.f;
        #pragma unroll
        for (int nt = 0; nt < 8; nt++) {
            s[nt][0] = __expf(s[nt][0] - mn0);
            s[nt][1] = __expf(s[nt][1] - mn0);
            s[nt][2] = __expf(s[nt][2] - mn1);
            s[nt][3] = __expf(s[nt][3] - mn1);
            rs0 += s[nt][0] + s[nt][1];
            rs1 += s[nt][2] + s[nt][3];
        }
        #pragma unroll
        for (int off = 1; off <= 2; off <<= 1) {
            rs0 += __shfl_xor_sync(0xffffffffu, rs0, off);
            rs1 += __shfl_xor_sync(0xffffffffu, rs1, off);
        }
        l0 = l0 * al0 + rs0;
        l1 = l1 * al1 + rs1;
        #pragma unroll
        for (int nt = 0; nt < 16; nt++) {
            o[nt][0] *= al0; o[nt][1] *= al0;
            o[nt][2] *= al1; o[nt][3] *= al1;
        }

        // load V tile over K
        __syncthreads();
        {
            const float* vp = Vp + (size_t)(kb + lrow) * DD + coff;
            #pragma unroll
            for (int j = 0; j < 16; j++) {
                float4 v = *(const float4*)(vp + 4 * j);
                uint4 u = { f2tf(v.x), f2tf(v.y), f2tf(v.z), f2tf(v.w) };
                *(uint4*)&KVs[lrow][coff + 4*j] = u;
            }
        }
        __syncthreads();

        // O += P V : convert P c-frags to a-frags via quad shuffles
        const int srcA = (lane & ~3) | (c >> 1);
        const int srcB = srcA + 2;
        #pragma unroll
        for (int ks = 0; ks < 8; ks++) {
            float v00 = s[ks][0], v01 = s[ks][1], v10 = s[ks][2], v11 = s[ks][3];
            float t00 = __shfl_sync(0xffffffffu, v00, srcA);
            float t01 = __shfl_sync(0xffffffffu, v01, srcA);
            float t02 = __shfl_sync(0xffffffffu, v00, srcB);
            float t03 = __shfl_sync(0xffffffffu, v01, srcB);
            float u00 = __shfl_sync(0xffffffffu, v10, srcA);
            float u01 = __shfl_sync(0xffffffffu, v11, srcA);
            float u02 = __shfl_sync(0xffffffffu, v10, srcB);
            float u03 = __shfl_sync(0xffffffffu, v11, srcB);
            uint32_t a[4];
            a[0] = f2tf((c & 1) ? t01 : t00);
            a[1] = f2tf((c & 1) ? u01 : u00);
            a[2] = f2tf((c & 1) ? t03 : t02);
            a[3] = f2tf((c & 1) ? u03 : u02);
            #pragma unroll
            for (int nt = 0; nt < 16; nt++) {
                uint32_t b0 = KVs[8*ks + c    ][nt*8 + g];
                uint32_t b1 = KVs[8*ks + c + 4][nt*8 + g];
                mma8(o[nt], a, b0, b1);
            }
        }
    }

    // epilogue: normalize, weight, store to g_o
    int token0 = b * SS + r0;
    int token1 = b * SS + r1;
    float w0 = g_hw[token0 * KK + kslot] / l0;
    float w1 = g_hw[token1 * KK + kslot] / l1;
    size_t base0 = ((size_t)token0 * KK + kslot) * DD;
    size_t base1 = ((size_t)token1 * KK + kslot) * DD;
    #pragma unroll
    for (int nt = 0; nt < 16; nt++) {
        int col = nt * 8 + 2 * c;
        float2 v0 = { o[nt][0] * w0, o[nt][1] * w0 };
        float2 v1 = { o[nt][2] * w1, o[nt][3] * w1 };
        *(float2*)&g_o[base0 + col] = v0;
        *(float2*)&g_o[base1 + col] = v1;
    }
}

// ---------------- kernel 5: output projection with tf32 MMA ----------------
__global__ __launch_bounds__(256) void outproj_mma_kernel(const float* __restrict__ Wo,
                                                          float* __restrict__ out) {
    const int rbase = blockIdx.x * 128;
    const int cbase = blockIdx.y * 128;

    __shared__ uint32_t Xs[32][136];
    __shared__ uint32_t Ws[32][132];

    const int tid = threadIdx.x;
    const int lane = tid & 31, warp = tid >> 5;
    const int g = lane >> 2, c = lane & 3;
    const int wr = (warp >> 1) * 32;
    const int wc = (warp & 1) * 64;

    const int myrow = tid >> 1;
    const int koff = (tid & 1) * 16;
    const float* arow = g_o + (size_t)(rbase + myrow) * EE + koff;

    float acc[2][8][4];
    #pragma unroll
    for (int mt = 0; mt < 2; mt++)
        #pragma unroll
        for (int nt = 0; nt < 8; nt++)
            #pragma unroll
            for (int q = 0; q < 4; q++) acc[mt][nt][q] = 0.f;

    for (int ec = 0; ec < EE; ec += 32) {
        __syncthreads();
        #pragma unroll
        for (int j = 0; j < 4; j++) {
            float4 v = *(const float4*)(arow + ec + 4 * j);
            Xs[koff + 4*j + 0][myrow] = f2tf(v.x);
            Xs[koff + 4*j + 1][myrow] = f2tf(v.y);
            Xs[koff + 4*j + 2][myrow] = f2tf(v.z);
            Xs[koff + 4*j + 3][myrow] = f2tf(v.w);
        }
        #pragma unroll
        for (int r = 0; r < 4; r++) {
            int i = tid + 256 * r;
            int k = i >> 5, n4 = (i & 31) * 4;
            float4 v = *(const float4*)(Wo + (size_t)(ec + k) * EE + cbase + n4);
            uint4 u = { f2tf(v.x), f2tf(v.y), f2tf(v.z), f2tf(v.w) };
            *(uint4*)&Ws[k][n4] = u;
        }
        __syncthreads();

        #pragma unroll
        for (int ks = 0; ks < 4; ks++) {
            uint32_t a[2][4];
            #pragma unroll
            for (int mt = 0; mt < 2; mt++) {
                int row = wr + mt * 16;
                a[mt][0] = Xs[ks*8 + c    ][row + g];
                a[mt][1] = Xs[ks*8 + c    ][row + g + 8];
                a[mt][2] = Xs[ks*8 + c + 4][row + g];
                a[mt][3] = Xs[ks*8 + c + 4][row + g + 8];
            }
            #pragma unroll
            for (int nt = 0; nt < 8; nt++) {
                uint32_t b0 = Ws[ks*8 + c    ][wc + nt*8 + g];
                uint32_t b1 = Ws[ks*8 + c + 4][wc + nt*8 + g];
                mma8(acc[0][nt], a[0], b0, b1);
                mma8(acc[1][nt], a[1], b0, b1);
            }
        }
    }

    #pragma unroll
    for (int mt = 0; mt < 2; mt++) {
        size_t row0 = rbase + wr + mt * 16 + g;
        size_t row1 = row0 + 8;
        #pragma unroll
        for (int nt = 0; nt < 8; nt++) {
            int col = cbase + wc + nt * 8 + 2 * c;
            float2 v0 = { acc[mt][nt][0], acc[mt][nt][1] };
            float2 v1 = { acc[mt][nt][2], acc[mt][nt][3] };
            *(float2*)&out[row0 * EE + col] = v0;
            *(float2*)&out[row1 * EE + col] = v1;
        }
    }
}

// ---------------- kernel 6: finalize ----------------
__global__ void finalize_kernel(float* __restrict__ out, int out_size) {
    __shared__ float s_bal[BB * HH];
    __shared__ float s_ent[256];
    const int tid = threadIdx.x;
    if (tid < BB * HH) {
        int b = tid / HH, h = tid % HH;
        float psum = 0.f, fcnt = 0.f;
        for (int s = 0; s < SS; s++) {
            psum += g_probs[(size_t)(b * SS + s) * HH + h];
            fcnt += (g_primary[b * SS + s] == h) ? 1.f : 0.f;
        }
        s_bal[tid] = (fcnt / SS) * (psum / SS);
    }
    float e = 0.f;
    for (int i = tid; i < BSZ; i += 256) e += g_ent[i];
    s_ent[tid] = e;
    __syncthreads();
    const int base = BSZ * EE;
    if (tid == 0 && out_size > base) {
        float bal = 0.f;
        for (int i = 0; i < BB * HH; i++) bal += s_bal[i];
        bal = (float)HH * (bal / BB);
        float ent = 0.f;
        for (int i = 0; i < 256; i++) ent += s_ent[i];
        ent /= (float)BSZ;
        out[out_size - 1] = bal - 0.01f * ent;
    }
    if (out_size > base) {
        for (int i = base + tid; i < out_size - 1; i += 256) out[i] = 0.f;
    }
}

// ---------------- launcher ----------------
extern "C" void kernel_launch(void* const* d_in, const int* in_sizes, int n_in,
                              void* d_out, int out_size) {
    const float* x  = (const float*)d_in[0];
    const float* Wq = (const float*)d_in[1];
    const float* Wk = (const float*)d_in[2];
    const float* Wv = (const float*)d_in[3];
    const float* Wr = (const float*)d_in[4];
    const float* Wo = (const float*)d_in[5];
    for (int i = 0; i < n_in; i++) {
        if (in_sizes[i] == EE * HH)      Wr = (const float*)d_in[i];
        if (in_sizes[i] == KK * DD * EE) Wo = (const float*)d_in[i];
    }
    float* out = (float*)d_out;

    zero_kernel<<<1, 32>>>();
    router_kernel<<<BSZ, 256>>>(x, Wr);
    proj_mma_kernel<<<dim3(32, HH, 3), 256>>>(x, Wq, Wk, Wv);
    rope_kernel<<<(BKH * SS * (DD / 2) + 255) / 256, 256>>>();
    attn_mma_kernel<<<dim3(BKH, SS / 64), 128>>>();
    outproj_mma_kernel<<<dim3(BSZ / 128, EE / 128), 256>>>(Wo, out);
    finalize_kernel<<<1, 256>>>(out, out_size);
}

// round 5
// speedup vs baseline: 2.5956x; 1.0827x over previous
#include <cuda_runtime.h>
#include <math.h>
#include <stdint.h>

#define BB 2
#define SS 2048
#define EE 1024
#define HH 32
#define KK 8
#define DD 128
#define BSZ (BB*SS)     // 4096 tokens
#define BKH (BB*KK)     // 16 head-slots

// ---------------- scratch ----------------
static __device__ float g_hw[BSZ*KK];
static __device__ float g_probs[BSZ*HH];
static __device__ float g_ent[BSZ];
static __device__ int   g_primary[BSZ];
static __device__ int   g_bcnt[HH];
static __device__ int   g_bucket[HH*BSZ];
static __device__ float g_q[(size_t)BKH*SS*DD];   // after rope: tf32 bits, pre-scaled
static __device__ float g_k[(size_t)BKH*SS*DD];   // after rope: tf32 bits
static __device__ float g_v[(size_t)BKH*SS*DD];   // tf32 bits (written by proj)
static __device__ float g_o[(size_t)BSZ*KK*DD];   // tf32 bits (written by attn)

// ---------------- helpers ----------------
__device__ __forceinline__ uint32_t f2tf(float f) {
    uint32_t u;
    asm("cvt.rna.tf32.f32 %0, %1;" : "=r"(u) : "f"(f));
    return u;
}
__device__ __forceinline__ void mma8(float* cc, const uint32_t* a, uint32_t b0, uint32_t b1) {
    asm volatile(
        "mma.sync.aligned.m16n8k8.row.col.f32.tf32.tf32.f32 "
        "{%0,%1,%2,%3},{%4,%5,%6,%7},{%8,%9},{%0,%1,%2,%3};\n"
        : "+f"(cc[0]), "+f"(cc[1]), "+f"(cc[2]), "+f"(cc[3])
        : "r"(a[0]), "r"(a[1]), "r"(a[2]), "r"(a[3]), "r"(b0), "r"(b1));
}
__device__ __forceinline__ void cp16(void* smem, const void* gmem) {
    uint32_t a = (uint32_t)__cvta_generic_to_shared(smem);
    asm volatile("cp.async.cg.shared.global [%0], [%1], 16;\n" :: "r"(a), "l"(gmem));
}
__device__ __forceinline__ void cp_commit() { asm volatile("cp.async.commit_group;\n"); }
template<int N> __device__ __forceinline__ void cp_wait() {
    asm volatile("cp.async.wait_group %0;\n" :: "n"(N));
}

// ---------------- kernel 0 ----------------
__global__ void zero_kernel() {
    if (threadIdx.x < HH) g_bcnt[threadIdx.x] = 0;
}

// ---------------- kernel 1: router (exact fp32) ----------------
__global__ __launch_bounds__(256) void router_kernel(const float* __restrict__ x,
                                                     const float* __restrict__ Wr) {
    const int token = blockIdx.x;
    __shared__ float xs[EE];
    __shared__ float part[8][HH];
    __shared__ float s_topv[KK];
    __shared__ int   s_topi[KK];
    const int tid = threadIdx.x;

    const float4* xv = (const float4*)(x + (size_t)token * EE);
    float4* xsv = (float4*)xs;
    for (int i = tid; i < EE/4; i += 256) xsv[i] = xv[i];
    __syncthreads();

    const int warp = tid >> 5, lane = tid & 31;
    float acc = 0.f;
    const int e0 = warp * 128;
    #pragma unroll 4
    for (int e = 0; e < 128; e++)
        acc = fmaf(xs[e0 + e], Wr[(size_t)(e0 + e) * HH + lane], acc);
    part[warp][lane] = acc;
    __syncthreads();

    if (warp == 0) {
        float logit = 0.f;
        #pragma unroll
        for (int w = 0; w < 8; w++) logit += part[w][lane];

        float m = logit;
        #pragma unroll
        for (int o = 16; o; o >>= 1) m = fmaxf(m, __shfl_xor_sync(0xffffffffu, m, o));
        float ex = expf(logit - m);
        float sum = ex;
        #pragma unroll
        for (int o = 16; o; o >>= 1) sum += __shfl_xor_sync(0xffffffffu, sum, o);
        float prob = ex / sum;
        g_probs[(size_t)token * HH + lane] = prob;
        float et = -prob * logf(prob + 1e-8f);
        #pragma unroll
        for (int o = 16; o; o >>= 1) et += __shfl_xor_sync(0xffffffffu, et, o);
        if (lane == 0) g_ent[token] = et;

        float cur = logit;
        for (int j = 0; j < KK; j++) {
            float bv = cur; int bi = lane;
            #pragma unroll
            for (int o = 16; o; o >>= 1) {
                float ov = __shfl_xor_sync(0xffffffffu, bv, o);
                int   oi = __shfl_xor_sync(0xffffffffu, bi, o);
                if (ov > bv || (ov == bv && oi < bi)) { bv = ov; bi = oi; }
            }
            if (lane == 0) { s_topv[j] = bv; s_topi[j] = bi; }
            if (lane == bi) cur = -INFINITY;
        }
        __syncwarp();

        if (lane < KK) {
            float tv = s_topv[lane];
            float e2 = expf(tv - s_topv[0]);
            float s2 = e2;
            #pragma unroll
            for (int o = 4; o; o >>= 1) s2 += __shfl_xor_sync(0x000000ffu, s2, o, 8);
            int hsel = s_topi[lane];
            g_hw[token * KK + lane] = e2 / s2;
            int pos = atomicAdd(&g_bcnt[hsel], 1);
            g_bucket[hsel * BSZ + pos] = token * KK + lane;
        }
        if (lane == 0) g_primary[token] = s_topi[0];
    }
}

// ---------------- kernel 2: bucketed gather projection, tf32 MMA + reg prefetch ----------------
__global__ __launch_bounds__(256) void proj_mma_kernel(const float* __restrict__ x,
                                                       const float* __restrict__ Wq,
                                                       const float* __restrict__ Wk,
                                                       const float* __restrict__ Wv) {
    const int h = blockIdx.y;
    const int cnt = g_bcnt[h];
    const int t0 = blockIdx.x * 128;
    if (t0 >= cnt) return;
    const int mat = blockIdx.z;
    const float* W = (mat == 0 ? Wq : mat == 1 ? Wk : Wv) + h * DD;
    float* dst = (mat == 0 ? g_q : mat == 1 ? g_k : g_v);

    __shared__ int codes[128];
    __shared__ uint32_t Xs[32][136];   // [k][row], tf32 bits
    __shared__ uint32_t Ws[32][132];   // [k][n],  tf32 bits

    const int tid = threadIdx.x;
    const int lane = tid & 31, warp = tid >> 5;
    const int g = lane >> 2, c = lane & 3;
    const int wr = (warp >> 1) * 32;
    const int wc = (warp & 1) * 64;

    if (tid < 128) {
        int ii = t0 + tid;
        codes[tid] = (ii < cnt) ? g_bucket[h * BSZ + ii] : -1;
    }
    __syncthreads();

    const int myrow = tid >> 1;
    const int koff = (tid & 1) * 16;
    int mycode = codes[myrow];
    const float* xrow = x + (size_t)(mycode >= 0 ? (mycode >> 3) : 0) * EE + koff;

    float acc[2][8][4];
    #pragma unroll
    for (int mt = 0; mt < 2; mt++)
        #pragma unroll
        for (int nt = 0; nt < 8; nt++)
            #pragma unroll
            for (int q = 0; q < 4; q++) acc[mt][nt][q] = 0.f;

    float4 px[4], pw[4];
    // prefetch chunk 0
    #pragma unroll
    for (int j = 0; j < 4; j++) px[j] = *(const float4*)(xrow + 4 * j);
    #pragma unroll
    for (int r = 0; r < 4; r++) {
        int i = tid + 256 * r;
        int k = i >> 5, n4 = (i & 31) * 4;
        pw[r] = *(const float4*)(W + (size_t)k * (HH * DD) + n4);
    }

    for (int ec = 0; ec < EE; ec += 32) {
        __syncthreads();
        // store prefetched regs -> smem (cvt to tf32)
        #pragma unroll
        for (int j = 0; j < 4; j++) {
            Xs[koff + 4*j + 0][myrow] = f2tf(px[j].x);
            Xs[koff + 4*j + 1][myrow] = f2tf(px[j].y);
            Xs[koff + 4*j + 2][myrow] = f2tf(px[j].z);
            Xs[koff + 4*j + 3][myrow] = f2tf(px[j].w);
        }
        #pragma unroll
        for (int r = 0; r < 4; r++) {
            int i = tid + 256 * r;
            int k = i >> 5, n4 = (i & 31) * 4;
            uint4 u = { f2tf(pw[r].x), f2tf(pw[r].y), f2tf(pw[r].z), f2tf(pw[r].w) };
            *(uint4*)&Ws[k][n4] = u;
        }
        __syncthreads();
        // prefetch next chunk while tensor pipe works
        if (ec + 32 < EE) {
            #pragma unroll
            for (int j = 0; j < 4; j++) px[j] = *(const float4*)(xrow + ec + 32 + 4 * j);
            #pragma unroll
            for (int r = 0; r < 4; r++) {
                int i = tid + 256 * r;
                int k = i >> 5, n4 = (i & 31) * 4;
                pw[r] = *(const float4*)(W + (size_t)(ec + 32 + k) * (HH * DD) + n4);
            }
        }

        #pragma unroll
        for (int ks = 0; ks < 4; ks++) {
            uint32_t a[2][4];
            #pragma unroll
            for (int mt = 0; mt < 2; mt++) {
                int row = wr + mt * 16;
                a[mt][0] = Xs[ks*8 + c    ][row + g];
                a[mt][1] = Xs[ks*8 + c    ][row + g + 8];
                a[mt][2] = Xs[ks*8 + c + 4][row + g];
                a[mt][3] = Xs[ks*8 + c + 4][row + g + 8];
            }
            #pragma unroll
            for (int nt = 0; nt < 8; nt++) {
                uint32_t b0 = Ws[ks*8 + c    ][wc + nt*8 + g];
                uint32_t b1 = Ws[ks*8 + c + 4][wc + nt*8 + g];
                mma8(acc[0][nt], a[0], b0, b1);
                mma8(acc[1][nt], a[1], b0, b1);
            }
        }
    }

    // epilogue: scatter rows; V stored as tf32 bits, Q/K as fp32 (rope converts later)
    #pragma unroll
    for (int mt = 0; mt < 2; mt++) {
        int r0 = wr + mt * 16 + g;
        int r1 = r0 + 8;
        int code0 = codes[r0], code1 = codes[r1];
        size_t base0 = 0, base1 = 0;
        if (code0 >= 0) {
            int token = code0 >> 3, slot = code0 & 7;
            base0 = ((size_t)(((token >> 11) * KK + slot) * SS + (token & (SS-1)))) * DD;
        }
        if (code1 >= 0) {
            int token = code1 >> 3, slot = code1 & 7;
            base1 = ((size_t)(((token >> 11) * KK + slot) * SS + (token & (SS-1)))) * DD;
        }
        #pragma unroll
        for (int nt = 0; nt < 8; nt++) {
            int col = wc + nt * 8 + 2 * c;
            if (mat == 2) {
                if (code0 >= 0) {
                    float2 v = { __uint_as_float(f2tf(acc[mt][nt][0])),
                                 __uint_as_float(f2tf(acc[mt][nt][1])) };
                    *(float2*)&dst[base0 + col] = v;
                }
                if (code1 >= 0) {
                    float2 v = { __uint_as_float(f2tf(acc[mt][nt][2])),
                                 __uint_as_float(f2tf(acc[mt][nt][3])) };
                    *(float2*)&dst[base1 + col] = v;
                }
            } else {
                if (code0 >= 0) { float2 v = { acc[mt][nt][0], acc[mt][nt][1] }; *(float2*)&dst[base0 + col] = v; }
                if (code1 >= 0) { float2 v = { acc[mt][nt][2], acc[mt][nt][3] }; *(float2*)&dst[base1 + col] = v; }
            }
        }
    }
}

// ---------------- kernel 3: RoPE; writes tf32 bits, folds 1/sqrt(D) into q ----------------
__global__ void rope_kernel() {
    int idx = blockIdx.x * blockDim.x + threadIdx.x;
    const int total = BKH * SS * (DD / 2);
    if (idx >= total) return;
    int d = idx & 63;
    int rest = idx >> 6;
    int s = rest & (SS - 1);
    float inv = expf(-(float)d * (9.210340371976184f / 64.f));
    float fr = (float)s * inv;
    float sn, cs;
    sincosf(fr, &sn, &cs);
    const float scale = 0.08838834764831843f;  // 1/sqrt(128)
    size_t i0 = ((size_t)rest << 7) + d;
    float q1 = g_q[i0], q2 = g_q[i0 + 64];
    g_q[i0]      = __uint_as_float(f2tf((q1 * cs - q2 * sn) * scale));
    g_q[i0 + 64] = __uint_as_float(f2tf((q2 * cs + q1 * sn) * scale));
    float k1 = g_k[i0], k2 = g_k[i0 + 64];
    g_k[i0]      = __uint_as_float(f2tf(k1 * cs - k2 * sn));
    g_k[i0 + 64] = __uint_as_float(f2tf(k2 * cs + k1 * sn));
}

// ---------------- kernel 4: flash attention, cp.async pipelined ----------------
// grid (16 slots, 32 q-tiles), block 128 = 4 warps. Dynamic smem: K + V buffers.
#define ATTN_SMEM (2 * 64 * 132 * 4)
__global__ __launch_bounds__(128, 2) void attn_mma_kernel() {
    extern __shared__ uint32_t sm_attn[];
    uint32_t (*Ks)[132] = (uint32_t(*)[132])sm_attn;
    uint32_t (*Vs)[132] = (uint32_t(*)[132])(sm_attn + 64 * 132);

    const int bk = blockIdx.x;
    const int qt = gridDim.y - 1 - blockIdx.y;     // big tiles first
    const int qbase = qt * 64;
    const int b = bk >> 3, kslot = bk & 7;
    const int tid = threadIdx.x;
    const int lane = tid & 31, warp = tid >> 5;
    const int g = lane >> 2, c = lane & 3;

    const uint32_t* Qp = (const uint32_t*)g_q + (size_t)bk * SS * DD;
    const uint32_t* Kp = (const uint32_t*)g_k + (size_t)bk * SS * DD;
    const uint32_t* Vp = (const uint32_t*)g_v + (size_t)bk * SS * DD;

    const int lrow = tid >> 1;
    const int coff = (tid & 1) * 64;

    // stage K0 immediately (overlaps with Q register loads)
    {
        const uint32_t* src = Kp + (size_t)lrow * DD + coff;
        #pragma unroll
        for (int j = 0; j < 16; j++) cp16(&Ks[lrow][coff + 4*j], src + 4*j);
        cp_commit();
    }

    // Q fragments: already tf32 bits, pre-scaled
    const int r0 = qbase + warp * 16 + g;
    const int r1 = r0 + 8;
    uint32_t qf[16][4];
    {
        const uint32_t* q0 = Qp + (size_t)r0 * DD;
        const uint32_t* q1 = Qp + (size_t)r1 * DD;
        #pragma unroll
        for (int ks = 0; ks < 16; ks++) {
            qf[ks][0] = q0[8*ks + c    ];
            qf[ks][1] = q1[8*ks + c    ];
            qf[ks][2] = q0[8*ks + c + 4];
            qf[ks][3] = q1[8*ks + c + 4];
        }
    }

    float o[16][4];
    #pragma unroll
    for (int nt = 0; nt < 16; nt++)
        #pragma unroll
        for (int q = 0; q < 4; q++) o[nt][q] = 0.f;
    float m0 = -INFINITY, m1 = -INFINITY, l0 = 0.f, l1 = 0.f;

    for (int kt = 0; kt <= qt; kt++) {
        const int kb = kt * 64;
        cp_wait<0>();            // K_kt ready (only pending group)
        __syncthreads();         // also: all warps done with V of previous iter

        // stage V_kt (overlaps with S compute)
        {
            const uint32_t* src = Vp + (size_t)(kb + lrow) * DD + coff;
            #pragma unroll
            for (int j = 0; j < 16; j++) cp16(&Vs[lrow][coff + 4*j], src + 4*j);
            cp_commit();
        }

        // S = Q K^T
        float s[8][4];
        #pragma unroll
        for (int nt = 0; nt < 8; nt++)
            #pragma unroll
            for (int q = 0; q < 4; q++) s[nt][q] = 0.f;
        #pragma unroll
        for (int ks = 0; ks < 16; ks++) {
            #pragma unroll
            for (int nt = 0; nt < 8; nt++) {
                uint32_t b0 = Ks[nt*8 + g][8*ks + c    ];
                uint32_t b1 = Ks[nt*8 + g][8*ks + c + 4];
                mma8(s[nt], qf[ks], b0, b1);
            }
        }
        __syncthreads();         // all warps done reading K

        // stage K_{kt+1} (overlaps with softmax + PV)
        if (kt < qt) {
            const uint32_t* src = Kp + (size_t)(kb + 64 + lrow) * DD + coff;
            #pragma unroll
            for (int j = 0; j < 16; j++) cp16(&Ks[lrow][coff + 4*j], src + 4*j);
            cp_commit();
        }

        // causal mask on diagonal tile
        if (kt == qt) {
            #pragma unroll
            for (int nt = 0; nt < 8; nt++) {
                int col = kb + nt * 8 + 2 * c;
                if (col     > r0) s[nt][0] = -INFINITY;
                if (col + 1 > r0) s[nt][1] = -INFINITY;
                if (col     > r1) s[nt][2] = -INFINITY;
                if (col + 1 > r1) s[nt][3] = -INFINITY;
            }
        }

        // online softmax (rows r0 / r1, quad-shared)
        float mx0 = -INFINITY, mx1 = -INFINITY;
        #pragma unroll
        for (int nt = 0; nt < 8; nt++) {
            mx0 = fmaxf(mx0, fmaxf(s[nt][0], s[nt][1]));
            mx1 = fmaxf(mx1, fmaxf(s[nt][2], s[nt][3]));
        }
        #pragma unroll
        for (int off = 1; off <= 2; off <<= 1) {
            mx0 = fmaxf(mx0, __shfl_xor_sync(0xffffffffu, mx0, off));
            mx1 = fmaxf(mx1, __shfl_xor_sync(0xffffffffu, mx1, off));
        }
        float mn0 = fmaxf(m0, mx0), mn1 = fmaxf(m1, mx1);
        float al0 = __expf(m0 - mn0), al1 = __expf(m1 - mn1);
        m0 = mn0; m1 = mn1;
        float rs0 = 0.f, rs1 = 0.f;
        #pragma unroll
        for (int nt = 0; nt < 8; nt++) {
            s[nt][0] = __expf(s[nt][0] - mn0);
            s[nt][1] = __expf(s[nt][1] - mn0);
            s[nt][2] = __expf(s[nt][2] - mn1);
            s[nt][3] = __expf(s[nt][3] - mn1);
            rs0 += s[nt][0] + s[nt][1];
            rs1 += s[nt][2] + s[nt][3];
        }
        #pragma unroll
        for (int off = 1; off <= 2; off <<= 1) {
            rs0 += __shfl_xor_sync(0xffffffffu, rs0, off);
            rs1 += __shfl_xor_sync(0xffffffffu, rs1, off);
        }
        l0 = l0 * al0 + rs0;
        l1 = l1 * al1 + rs1;
        #pragma unroll
        for (int nt = 0; nt < 16; nt++) {
            o[nt][0] *= al0; o[nt][1] *= al0;
            o[nt][2] *= al1; o[nt][3] *= al1;
        }

        // wait for V_kt (K_{kt+1} may still be in flight)
        if (kt < qt) cp_wait<1>(); else cp_wait<0>();
        __syncthreads();

        // O += P V : convert P c-frags to a-frags via quad shuffles
        const int srcA = (lane & ~3) | (c >> 1);
        const int srcB = srcA + 2;
        #pragma unroll
        for (int ks = 0; ks < 8; ks++) {
            float v00 = s[ks][0], v01 = s[ks][1], v10 = s[ks][2], v11 = s[ks][3];
            float t00 = __shfl_sync(0xffffffffu, v00, srcA);
            float t01 = __shfl_sync(0xffffffffu, v01, srcA);
            float t02 = __shfl_sync(0xffffffffu, v00, srcB);
            float t03 = __shfl_sync(0xffffffffu, v01, srcB);
            float u00 = __shfl_sync(0xffffffffu, v10, srcA);
            float u01 = __shfl_sync(0xffffffffu, v11, srcA);
            float u02 = __shfl_sync(0xffffffffu, v10, srcB);
            float u03 = __shfl_sync(0xffffffffu, v11, srcB);
            uint32_t a[4];
            a[0] = f2tf((c & 1) ? t01 : t00);
            a[1] = f2tf((c & 1) ? u01 : u00);
            a[2] = f2tf((c & 1) ? t03 : t02);
            a[3] = f2tf((c & 1) ? u03 : u02);
            #pragma unroll
            for (int nt = 0; nt < 16; nt++) {
                uint32_t b0 = Vs[8*ks + c    ][nt*8 + g];
                uint32_t b1 = Vs[8*ks + c + 4][nt*8 + g];
                mma8(o[nt], a, b0, b1);
            }
        }
    }

    // epilogue: normalize, weight, store tf32 bits to g_o
    int token0 = b * SS + r0;
    int token1 = b * SS + r1;
    float w0 = g_hw[token0 * KK + kslot] / l0;
    float w1 = g_hw[token1 * KK + kslot] / l1;
    size_t base0 = ((size_t)token0 * KK + kslot) * DD;
    size_t base1 = ((size_t)token1 * KK + kslot) * DD;
    uint32_t* go = (uint32_t*)g_o;
    #pragma unroll
    for (int nt = 0; nt < 16; nt++) {
        int col = nt * 8 + 2 * c;
        uint2 v0 = { f2tf(o[nt][0] * w0), f2tf(o[nt][1] * w0) };
        uint2 v1 = { f2tf(o[nt][2] * w1), f2tf(o[nt][3] * w1) };
        *(uint2*)&go[base0 + col] = v0;
        *(uint2*)&go[base1 + col] = v1;
    }
}

// ---------------- kernel 5: output projection, tf32 MMA + reg prefetch ----------------
__global__ __launch_bounds__(256) void outproj_mma_kernel(const float* __restrict__ Wo,
                                                          float* __restrict__ out) {
    const int rbase = blockIdx.x * 128;
    const int cbase = blockIdx.y * 128;

    __shared__ uint32_t Xs[32][136];
    __shared__ uint32_t Ws[32][132];

    const int tid = threadIdx.x;
    const int lane = tid & 31, warp = tid >> 5;
    const int g = lane >> 2, c = lane & 3;
    const int wr = (warp >> 1) * 32;
    const int wc = (warp & 1) * 64;

    const int myrow = tid >> 1;
    const int koff = (tid & 1) * 16;
    const uint32_t* arow = (const uint32_t*)g_o + (size_t)(rbase + myrow) * EE + koff;

    float acc[2][8][4];
    #pragma unroll
    for (int mt = 0; mt < 2; mt++)
        #pragma unroll
        for (int nt = 0; nt < 8; nt++)
            #pragma unroll
            for (int q = 0; q < 4; q++) acc[mt][nt][q] = 0.f;

    uint4  px[4];
    float4 pw[4];
    #pragma unroll
    for (int j = 0; j < 4; j++) px[j] = *(const uint4*)(arow + 4 * j);
    #pragma unroll
    for (int r = 0; r < 4; r++) {
        int i = tid + 256 * r;
        int k = i >> 5, n4 = (i & 31) * 4;
        pw[r] = *(const float4*)(Wo + (size_t)k * EE + cbase + n4);
    }

    for (int ec = 0; ec < EE; ec += 32) {
        __syncthreads();
        #pragma unroll
        for (int j = 0; j < 4; j++) {
            Xs[koff + 4*j + 0][myrow] = px[j].x;   // already tf32 bits
            Xs[koff + 4*j + 1][myrow] = px[j].y;
            Xs[koff + 4*j + 2][myrow] = px[j].z;
            Xs[koff + 4*j + 3][myrow] = px[j].w;
        }
        #pragma unroll
        for (int r = 0; r < 4; r++) {
            int i = tid + 256 * r;
            int k = i >> 5, n4 = (i & 31) * 4;
            uint4 u = { f2tf(pw[r].x), f2tf(pw[r].y), f2tf(pw[r].z), f2tf(pw[r].w) };
            *(uint4*)&Ws[k][n4] = u;
        }
        __syncthreads();
        if (ec + 32 < EE) {
            #pragma unroll
            for (int j = 0; j < 4; j++) px[j] = *(const uint4*)(arow + ec + 32 + 4 * j);
            #pragma unroll
            for (int r = 0; r < 4; r++) {
                int i = tid + 256 * r;
                int k = i >> 5, n4 = (i & 31) * 4;
                pw[r] = *(const float4*)(Wo + (size_t)(ec + 32 + k) * EE + cbase + n4);
            }
        }

        #pragma unroll
        for (int ks = 0; ks < 4; ks++) {
            uint32_t a[2][4];
            #pragma unroll
            for (int mt = 0; mt < 2; mt++) {
                int row = wr + mt * 16;
                a[mt][0] = Xs[ks*8 + c    ][row + g];
                a[mt][1] = Xs[ks*8 + c    ][row + g + 8];
                a[mt][2] = Xs[ks*8 + c + 4][row + g];
                a[mt][3] = Xs[ks*8 + c + 4][row + g + 8];
            }
            #pragma unroll
            for (int nt = 0; nt < 8; nt++) {
                uint32_t b0 = Ws[ks*8 + c    ][wc + nt*8 + g];
                uint32_t b1 = Ws[ks*8 + c + 4][wc + nt*8 + g];
                mma8(acc[0][nt], a[0], b0, b1);
                mma8(acc[1][nt], a[1], b0, b1);
            }
        }
    }

    #pragma unroll
    for (int mt = 0; mt < 2; mt++) {
        size_t row0 = rbase + wr + mt * 16 + g;
        size_t row1 = row0 + 8;
        #pragma unroll
        for (int nt = 0; nt < 8; nt++) {
            int col = cbase + wc + nt * 8 + 2 * c;
            float2 v0 = { acc[mt][nt][0], acc[mt][nt][1] };
            float2 v1 = { acc[mt][nt][2], acc[mt][nt][3] };
            *(float2*)&out[row0 * EE + col] = v0;
            *(float2*)&out[row1 * EE + col] = v1;
        }
    }
}

// ---------------- kernel 6: finalize ----------------
__global__ void finalize_kernel(float* __restrict__ out, int out_size) {
    __shared__ float s_bal[BB * HH];
    __shared__ float s_ent[256];
    const int tid = threadIdx.x;
    if (tid < BB * HH) {
        int b = tid / HH, h = tid % HH;
        float psum = 0.f, fcnt = 0.f;
        for (int s = 0; s < SS; s++) {
            psum += g_probs[(size_t)(b * SS + s) * HH + h];
            fcnt += (g_primary[b * SS + s] == h) ? 1.f : 0.f;
        }
        s_bal[tid] = (fcnt / SS) * (psum / SS);
    }
    float e = 0.f;
    for (int i = tid; i < BSZ; i += 256) e += g_ent[i];
    s_ent[tid] = e;
    __syncthreads();
    const int base = BSZ * EE;
    if (tid == 0 && out_size > base) {
        float bal = 0.f;
        for (int i = 0; i < BB * HH; i++) bal += s_bal[i];
        bal = (float)HH * (bal / BB);
        float ent = 0.f;
        for (int i = 0; i < 256; i++) ent += s_ent[i];
        ent /= (float)BSZ;
        out[out_size - 1] = bal - 0.01f * ent;
    }
    if (out_size > base) {
        for (int i = base + tid; i < out_size - 1; i += 256) out[i] = 0.f;
    }
}

// ---------------- launcher ----------------
extern "C" void kernel_launch(void* const* d_in, const int* in_sizes, int n_in,
                              void* d_out, int out_size) {
    const float* x  = (const float*)d_in[0];
    const float* Wq = (const float*)d_in[1];
    const float* Wk = (const float*)d_in[2];
    const float* Wv = (const float*)d_in[3];
    const float* Wr = (const float*)d_in[4];
    const float* Wo = (const float*)d_in[5];
    for (int i = 0; i < n_in; i++) {
        if (in_sizes[i] == EE * HH)      Wr = (const float*)d_in[i];
        if (in_sizes[i] == KK * DD * EE) Wo = (const float*)d_in[i];
    }
    float* out = (float*)d_out;

    // idempotent host-side attribute set (not a stream op; capture-legal)
    static int smem_set = 0;
    if (!smem_set) {
        cudaFuncSetAttribute(attn_mma_kernel,
                             cudaFuncAttributeMaxDynamicSharedMemorySize, ATTN_SMEM);
        smem_set = 1;
    }

    zero_kernel<<<1, 32>>>();
    router_kernel<<<BSZ, 256>>>(x, Wr);
    proj_mma_kernel<<<dim3(32, HH, 3), 256>>>(x, Wq, Wk, Wv);
    rope_kernel<<<(BKH * SS * (DD / 2) + 255) / 256, 256>>>();
    attn_mma_kernel<<<dim3(BKH, SS / 64), 128, ATTN_SMEM>>>();
    outproj_mma_kernel<<<dim3(BSZ / 128, EE / 128), 256>>>(Wo, out);
    finalize_kernel<<<1, 256>>>(out, out_size);
}

// round 6
// speedup vs baseline: 3.1663x; 1.2199x over previous
#include <cuda_runtime.h>
#include <math.h>
#include <stdint.h>

#define BB 2
#define SS 2048
#define EE 1024
#define HH 32
#define KK 8
#define DD 128
#define BSZ (BB*SS)     // 4096 tokens
#define BKH (BB*KK)     // 16 head-slots

// ---------------- scratch ----------------
static __device__ float g_hw[BSZ*KK];
static __device__ float g_probs[BSZ*HH];
static __device__ float g_ent[BSZ];
static __device__ int   g_primary[BSZ];
static __device__ int   g_bcnt[HH];
static __device__ int   g_bucket[HH*BSZ];
static __device__ float g_q[(size_t)BKH*SS*DD];   // after rope: tf32 bits, pre-scaled by (1/sqrt(D))*log2(e)
static __device__ float g_k[(size_t)BKH*SS*DD];   // after rope: tf32 bits
static __device__ float g_v[(size_t)BKH*SS*DD];   // tf32 bits (written by proj)
static __device__ float g_o[(size_t)BSZ*KK*DD];   // tf32 bits (written by attn)

// ---------------- helpers ----------------
__device__ __forceinline__ uint32_t f2tf(float f) {
    uint32_t u;
    asm("cvt.rna.tf32.f32 %0, %1;" : "=r"(u) : "f"(f));
    return u;
}
__device__ __forceinline__ float fexp2(float x) {
    float y;
    asm("ex2.approx.f32 %0, %1;" : "=f"(y) : "f"(x));
    return y;
}
__device__ __forceinline__ void mma8(float* cc, const uint32_t* a, uint32_t b0, uint32_t b1) {
    asm volatile(
        "mma.sync.aligned.m16n8k8.row.col.f32.tf32.tf32.f32 "
        "{%0,%1,%2,%3},{%4,%5,%6,%7},{%8,%9},{%0,%1,%2,%3};\n"
        : "+f"(cc[0]), "+f"(cc[1]), "+f"(cc[2]), "+f"(cc[3])
        : "r"(a[0]), "r"(a[1]), "r"(a[2]), "r"(a[3]), "r"(b0), "r"(b1));
}
__device__ __forceinline__ void cp16(void* smem, const void* gmem) {
    uint32_t a = (uint32_t)__cvta_generic_to_shared(smem);
    asm volatile("cp.async.cg.shared.global [%0], [%1], 16;\n" :: "r"(a), "l"(gmem));
}
__device__ __forceinline__ void cp_commit() { asm volatile("cp.async.commit_group;\n"); }
template<int N> __device__ __forceinline__ void cp_wait() {
    asm volatile("cp.async.wait_group %0;\n" :: "n"(N));
}

// ---------------- kernel 0 ----------------
__global__ void zero_kernel() {
    if (threadIdx.x < HH) g_bcnt[threadIdx.x] = 0;
}

// ---------------- kernel 1: router (exact fp32) ----------------
__global__ __launch_bounds__(256) void router_kernel(const float* __restrict__ x,
                                                     const float* __restrict__ Wr) {
    const int token = blockIdx.x;
    __shared__ float xs[EE];
    __shared__ float part[8][HH];
    __shared__ float s_topv[KK];
    __shared__ int   s_topi[KK];
    const int tid = threadIdx.x;

    const float4* xv = (const float4*)(x + (size_t)token * EE);
    float4* xsv = (float4*)xs;
    for (int i = tid; i < EE/4; i += 256) xsv[i] = xv[i];
    __syncthreads();

    const int warp = tid >> 5, lane = tid & 31;
    float acc = 0.f;
    const int e0 = warp * 128;
    #pragma unroll 4
    for (int e = 0; e < 128; e++)
        acc = fmaf(xs[e0 + e], Wr[(size_t)(e0 + e) * HH + lane], acc);
    part[warp][lane] = acc;
    __syncthreads();

    if (warp == 0) {
        float logit = 0.f;
        #pragma unroll
        for (int w = 0; w < 8; w++) logit += part[w][lane];

        float m = logit;
        #pragma unroll
        for (int o = 16; o; o >>= 1) m = fmaxf(m, __shfl_xor_sync(0xffffffffu, m, o));
        float ex = expf(logit - m);
        float sum = ex;
        #pragma unroll
        for (int o = 16; o; o >>= 1) sum += __shfl_xor_sync(0xffffffffu, sum, o);
        float prob = ex / sum;
        g_probs[(size_t)token * HH + lane] = prob;
        float et = -prob * logf(prob + 1e-8f);
        #pragma unroll
        for (int o = 16; o; o >>= 1) et += __shfl_xor_sync(0xffffffffu, et, o);
        if (lane == 0) g_ent[token] = et;

        float cur = logit;
        for (int j = 0; j < KK; j++) {
            float bv = cur; int bi = lane;
            #pragma unroll
            for (int o = 16; o; o >>= 1) {
                float ov = __shfl_xor_sync(0xffffffffu, bv, o);
                int   oi = __shfl_xor_sync(0xffffffffu, bi, o);
                if (ov > bv || (ov == bv && oi < bi)) { bv = ov; bi = oi; }
            }
            if (lane == 0) { s_topv[j] = bv; s_topi[j] = bi; }
            if (lane == bi) cur = -INFINITY;
        }
        __syncwarp();

        if (lane < KK) {
            float tv = s_topv[lane];
            float e2 = expf(tv - s_topv[0]);
            float s2 = e2;
            #pragma unroll
            for (int o = 4; o; o >>= 1) s2 += __shfl_xor_sync(0x000000ffu, s2, o, 8);
            int hsel = s_topi[lane];
            g_hw[token * KK + lane] = e2 / s2;
            int pos = atomicAdd(&g_bcnt[hsel], 1);
            g_bucket[hsel * BSZ + pos] = token * KK + lane;
        }
        if (lane == 0) g_primary[token] = s_topi[0];
    }
}

// ---------------- kernel 2: bucketed gather projection ----------------
// Double-buffered smem, 1 sync/chunk. tile 128x128, kc=32, 8 warps.
#define PROJ_SMEM (4 * 32 * 136 * 4)   // X0,X1,W0,W1 each 32x136 words
__global__ __launch_bounds__(256) void proj_mma_kernel(const float* __restrict__ x,
                                                       const float* __restrict__ Wq,
                                                       const float* __restrict__ Wk,
                                                       const float* __restrict__ Wv) {
    const int h = blockIdx.y;
    const int cnt = g_bcnt[h];
    const int t0 = blockIdx.x * 128;
    if (t0 >= cnt) return;
    const int mat = blockIdx.z;
    const float* W = (mat == 0 ? Wq : mat == 1 ? Wk : Wv) + h * DD;
    float* dst = (mat == 0 ? g_q : mat == 1 ? g_k : g_v);

    extern __shared__ uint32_t psm[];
    uint32_t (*Xb[2])[136] = { (uint32_t(*)[136])psm,
                               (uint32_t(*)[136])(psm + 4352) };
    uint32_t (*Wb[2])[136] = { (uint32_t(*)[136])(psm + 8704),
                               (uint32_t(*)[136])(psm + 13056) };
    __shared__ int codes[128];

    const int tid = threadIdx.x;
    const int lane = tid & 31, warp = tid >> 5;
    const int g = lane >> 2, c = lane & 3;
    const int wr = (warp >> 1) * 32;
    const int wc = (warp & 1) * 64;

    if (tid < 128) {
        int ii = t0 + tid;
        codes[tid] = (ii < cnt) ? g_bucket[h * BSZ + ii] : -1;
    }
    __syncthreads();

    const int myrow = tid >> 1;
    const int koff = (tid & 1) * 16;
    int mycode = codes[myrow];
    const float* xrow = x + (size_t)(mycode >= 0 ? (mycode >> 3) : 0) * EE + koff;
    const int wk = tid >> 5;            // W stage: row = wk + 8r? use i-mapping below

    float acc[2][8][4];
    #pragma unroll
    for (int mt = 0; mt < 2; mt++)
        #pragma unroll
        for (int nt = 0; nt < 8; nt++)
            #pragma unroll
            for (int q = 0; q < 4; q++) acc[mt][nt][q] = 0.f;

    float4 px[4], pw[4];
    // prefetch + store chunk 0 into buf0
    #pragma unroll
    for (int j = 0; j < 4; j++) px[j] = *(const float4*)(xrow + 4 * j);
    #pragma unroll
    for (int r = 0; r < 4; r++) {
        int i = tid + 256 * r;
        int k = i >> 5, n4 = (i & 31) * 4;
        pw[r] = *(const float4*)(W + (size_t)k * (HH * DD) + n4);
    }
    {
        uint32_t (*Xs)[136] = Xb[0];
        uint32_t (*Ws)[136] = Wb[0];
        #pragma unroll
        for (int j = 0; j < 4; j++) {
            Xs[koff + 4*j + 0][myrow] = f2tf(px[j].x);
            Xs[koff + 4*j + 1][myrow] = f2tf(px[j].y);
            Xs[koff + 4*j + 2][myrow] = f2tf(px[j].z);
            Xs[koff + 4*j + 3][myrow] = f2tf(px[j].w);
        }
        #pragma unroll
        for (int r = 0; r < 4; r++) {
            int i = tid + 256 * r;
            int k = i >> 5, n4 = (i & 31) * 4;
            uint4 u = { f2tf(pw[r].x), f2tf(pw[r].y), f2tf(pw[r].z), f2tf(pw[r].w) };
            *(uint4*)&Ws[k][n4] = u;
        }
    }
    __syncthreads();

    for (int cch = 0; cch < 32; cch++) {
        // prefetch regs for next chunk (LDG latency hidden by MMA below)
        if (cch + 1 < 32) {
            int ec = (cch + 1) * 32;
            #pragma unroll
            for (int j = 0; j < 4; j++) px[j] = *(const float4*)(xrow + ec + 4 * j);
            #pragma unroll
            for (int r = 0; r < 4; r++) {
                int i = tid + 256 * r;
                int k = i >> 5, n4 = (i & 31) * 4;
                pw[r] = *(const float4*)(W + (size_t)(ec + k) * (HH * DD) + n4);
            }
        }
        {
            uint32_t (*Xs)[136] = Xb[cch & 1];
            uint32_t (*Ws)[136] = Wb[cch & 1];
            #pragma unroll
            for (int ks = 0; ks < 4; ks++) {
                uint32_t a[2][4];
                #pragma unroll
                for (int mt = 0; mt < 2; mt++) {
                    int row = wr + mt * 16;
                    a[mt][0] = Xs[ks*8 + c    ][row + g];
                    a[mt][1] = Xs[ks*8 + c    ][row + g + 8];
                    a[mt][2] = Xs[ks*8 + c + 4][row + g];
                    a[mt][3] = Xs[ks*8 + c + 4][row + g + 8];
                }
                #pragma unroll
                for (int nt = 0; nt < 8; nt++) {
                    uint32_t b0 = Ws[ks*8 + c    ][wc + nt*8 + g];
                    uint32_t b1 = Ws[ks*8 + c + 4][wc + nt*8 + g];
                    mma8(acc[0][nt], a[0], b0, b1);
                    mma8(acc[1][nt], a[1], b0, b1);
                }
            }
        }
        // store next chunk into other buffer (its last reader finished before prev sync)
        if (cch + 1 < 32) {
            uint32_t (*Xs)[136] = Xb[(cch + 1) & 1];
            uint32_t (*Ws)[136] = Wb[(cch + 1) & 1];
            #pragma unroll
            for (int j = 0; j < 4; j++) {
                Xs[koff + 4*j + 0][myrow] = f2tf(px[j].x);
                Xs[koff + 4*j + 1][myrow] = f2tf(px[j].y);
                Xs[koff + 4*j + 2][myrow] = f2tf(px[j].z);
                Xs[koff + 4*j + 3][myrow] = f2tf(px[j].w);
            }
            #pragma unroll
            for (int r = 0; r < 4; r++) {
                int i = tid + 256 * r;
                int k = i >> 5, n4 = (i & 31) * 4;
                uint4 u = { f2tf(pw[r].x), f2tf(pw[r].y), f2tf(pw[r].z), f2tf(pw[r].w) };
                *(uint4*)&Ws[k][n4] = u;
            }
        }
        __syncthreads();
    }

    // epilogue: scatter rows; V stored as tf32 bits, Q/K as fp32 (rope converts later)
    #pragma unroll
    for (int mt = 0; mt < 2; mt++) {
        int r0 = wr + mt * 16 + g;
        int r1 = r0 + 8;
        int code0 = codes[r0], code1 = codes[r1];
        size_t base0 = 0, base1 = 0;
        if (code0 >= 0) {
            int token = code0 >> 3, slot = code0 & 7;
            base0 = ((size_t)(((token >> 11) * KK + slot) * SS + (token & (SS-1)))) * DD;
        }
        if (code1 >= 0) {
            int token = code1 >> 3, slot = code1 & 7;
            base1 = ((size_t)(((token >> 11) * KK + slot) * SS + (token & (SS-1)))) * DD;
        }
        #pragma unroll
        for (int nt = 0; nt < 8; nt++) {
            int col = wc + nt * 8 + 2 * c;
            if (mat == 2) {
                if (code0 >= 0) {
                    float2 v = { __uint_as_float(f2tf(acc[mt][nt][0])),
                                 __uint_as_float(f2tf(acc[mt][nt][1])) };
                    *(float2*)&dst[base0 + col] = v;
                }
                if (code1 >= 0) {
                    float2 v = { __uint_as_float(f2tf(acc[mt][nt][2])),
                                 __uint_as_float(f2tf(acc[mt][nt][3])) };
                    *(float2*)&dst[base1 + col] = v;
                }
            } else {
                if (code0 >= 0) { float2 v = { acc[mt][nt][0], acc[mt][nt][1] }; *(float2*)&dst[base0 + col] = v; }
                if (code1 >= 0) { float2 v = { acc[mt][nt][2], acc[mt][nt][3] }; *(float2*)&dst[base1 + col] = v; }
            }
        }
    }
}

// ---------------- kernel 3: RoPE; writes tf32 bits; q gets (1/sqrt(D))*log2(e) ----------------
__global__ void rope_kernel() {
    int idx = blockIdx.x * blockDim.x + threadIdx.x;
    const int total = BKH * SS * (DD / 2);
    if (idx >= total) return;
    int d = idx & 63;
    int rest = idx >> 6;
    int s = rest & (SS - 1);
    float inv = expf(-(float)d * (9.210340371976184f / 64.f));
    float fr = (float)s * inv;
    float sn, cs;
    sincosf(fr, &sn, &cs);
    const float scale = 0.12751691579231338f;  // (1/sqrt(128)) * log2(e)
    size_t i0 = ((size_t)rest << 7) + d;
    float q1 = g_q[i0], q2 = g_q[i0 + 64];
    g_q[i0]      = __uint_as_float(f2tf((q1 * cs - q2 * sn) * scale));
    g_q[i0 + 64] = __uint_as_float(f2tf((q2 * cs + q1 * sn) * scale));
    float k1 = g_k[i0], k2 = g_k[i0 + 64];
    g_k[i0]      = __uint_as_float(f2tf(k1 * cs - k2 * sn));
    g_k[i0 + 64] = __uint_as_float(f2tf(k2 * cs + k1 * sn));
}

// ---------------- kernel 4: flash attention, q-tile 128, 8 warps, cp.async ----------------
// Ks: 64x132 (conflict-free for S B-frags), Vs: 64x136 (conflict-free for PV B-frags)
#define ATTN_SMEM ((64*132 + 64*136) * 4)
__global__ __launch_bounds__(256, 1) void attn_mma_kernel() {
    extern __shared__ uint32_t sm_attn[];
    uint32_t (*Ks)[132] = (uint32_t(*)[132])sm_attn;
    uint32_t (*Vs)[136] = (uint32_t(*)[136])(sm_attn + 64 * 132);

    const int bk = blockIdx.x;
    const int qt = gridDim.y - 1 - blockIdx.y;     // big tiles first
    const int qbase = qt * 128;
    const int b = bk >> 3, kslot = bk & 7;
    const int tid = threadIdx.x;
    const int lane = tid & 31, warp = tid >> 5;
    const int g = lane >> 2, c = lane & 3;

    const uint32_t* Qp = (const uint32_t*)g_q + (size_t)bk * SS * DD;
    const uint32_t* Kp = (const uint32_t*)g_k + (size_t)bk * SS * DD;
    const uint32_t* Vp = (const uint32_t*)g_v + (size_t)bk * SS * DD;

    const int lrow = tid >> 2;            // 0..63
    const int coff = (tid & 3) * 32;      // 0,32,64,96

    // stage K0 immediately
    {
        const uint32_t* src = Kp + (size_t)lrow * DD + coff;
        #pragma unroll
        for (int j = 0; j < 8; j++) cp16(&Ks[lrow][coff + 4*j], src + 4*j);
        cp_commit();
    }

    // Q fragments: tf32 bits, pre-scaled (incl log2e)
    const int r0 = qbase + warp * 16 + g;
    const int r1 = r0 + 8;
    uint32_t qf[16][4];
    {
        const uint32_t* q0 = Qp + (size_t)r0 * DD;
        const uint32_t* q1 = Qp + (size_t)r1 * DD;
        #pragma unroll
        for (int ks = 0; ks < 16; ks++) {
            qf[ks][0] = q0[8*ks + c    ];
            qf[ks][1] = q1[8*ks + c    ];
            qf[ks][2] = q0[8*ks + c + 4];
            qf[ks][3] = q1[8*ks + c + 4];
        }
    }

    float o[16][4];
    #pragma unroll
    for (int nt = 0; nt < 16; nt++)
        #pragma unroll
        for (int q = 0; q < 4; q++) o[nt][q] = 0.f;
    float m0 = -INFINITY, m1 = -INFINITY, l0 = 0.f, l1 = 0.f;

    const int nkt = 2 * qt + 2;          // kv tiles of 64 covering qbase+128 rows
    const int wlast = qbase + warp * 16 + 16;   // first kb that is fully masked for this warp

    for (int kt = 0; kt < nkt; kt++) {
        const int kb = kt * 64;
        const bool act = (kb < wlast);
        cp_wait<0>();
        __syncthreads();

        // stage V_kt (overlaps S compute)
        {
            const uint32_t* src = Vp + (size_t)(kb + lrow) * DD + coff;
            #pragma unroll
            for (int j = 0; j < 8; j++) cp16(&Vs[lrow][coff + 4*j], src + 4*j);
            cp_commit();
        }

        float s[8][4];
        if (act) {
            #pragma unroll
            for (int nt = 0; nt < 8; nt++)
                #pragma unroll
                for (int q = 0; q < 4; q++) s[nt][q] = 0.f;
            #pragma unroll
            for (int ks = 0; ks < 16; ks++) {
                #pragma unroll
                for (int nt = 0; nt < 8; nt++) {
                    uint32_t b0 = Ks[nt*8 + g][8*ks + c    ];
                    uint32_t b1 = Ks[nt*8 + g][8*ks + c + 4];
                    mma8(s[nt], qf[ks], b0, b1);
                }
            }
        }
        __syncthreads();         // all warps done reading K

        // stage K_{kt+1} (overlaps softmax + PV)
        if (kt + 1 < nkt) {
            const uint32_t* src = Kp + (size_t)(kb + 64 + lrow) * DD + coff;
            #pragma unroll
            for (int j = 0; j < 8; j++) cp16(&Ks[lrow][coff + 4*j], src + 4*j);
            cp_commit();
        }

        if (act) {
            // causal mask if this tile touches the diagonal for this thread's rows
            if (kb + 63 > r0) {
                #pragma unroll
                for (int nt = 0; nt < 8; nt++) {
                    int col = kb + nt * 8 + 2 * c;
                    if (col     > r0) s[nt][0] = -INFINITY;
                    if (col + 1 > r0) s[nt][1] = -INFINITY;
                    if (col     > r1) s[nt][2] = -INFINITY;
                    if (col + 1 > r1) s[nt][3] = -INFINITY;
                }
            }
            // online softmax in base-2 (log2e folded into q scale)
            float mx0 = -INFINITY, mx1 = -INFINITY;
            #pragma unroll
            for (int nt = 0; nt < 8; nt++) {
                mx0 = fmaxf(mx0, fmaxf(s[nt][0], s[nt][1]));
                mx1 = fmaxf(mx1, fmaxf(s[nt][2], s[nt][3]));
            }
            #pragma unroll
            for (int off = 1; off <= 2; off <<= 1) {
                mx0 = fmaxf(mx0, __shfl_xor_sync(0xffffffffu, mx0, off));
                mx1 = fmaxf(mx1, __shfl_xor_sync(0xffffffffu, mx1, off));
            }
            float mn0 = fmaxf(m0, mx0), mn1 = fmaxf(m1, mx1);
            float al0 = fexp2(m0 - mn0), al1 = fexp2(m1 - mn1);
            m0 = mn0; m1 = mn1;
            float rs0 = 0.f, rs1 = 0.f;
            #pragma unroll
            for (int nt = 0; nt < 8; nt++) {
                s[nt][0] = fexp2(s[nt][0] - mn0);
                s[nt][1] = fexp2(s[nt][1] - mn0);
                s[nt][2] = fexp2(s[nt][2] - mn1);
                s[nt][3] = fexp2(s[nt][3] - mn1);
                rs0 += s[nt][0] + s[nt][1];
                rs1 += s[nt][2] + s[nt][3];
            }
            #pragma unroll
            for (int off = 1; off <= 2; off <<= 1) {
                rs0 += __shfl_xor_sync(0xffffffffu, rs0, off);
                rs1 += __shfl_xor_sync(0xffffffffu, rs1, off);
            }
            l0 = l0 * al0 + rs0;
            l1 = l1 * al1 + rs1;
            #pragma unroll
            for (int nt = 0; nt < 16; nt++) {
                o[nt][0] *= al0; o[nt][1] *= al0;
                o[nt][2] *= al1; o[nt][3] *= al1;
            }
        }

        // wait for V_kt (K_{kt+1} may still be in flight)
        if (kt + 1 < nkt) cp_wait<1>(); else cp_wait<0>();
        __syncthreads();

        if (act) {
            // O += P V : c-frag -> a-frag via quad shuffles
            const int srcA = (lane & ~3) | (c >> 1);
            const int srcB = srcA + 2;
            #pragma unroll
            for (int ks = 0; ks < 8; ks++) {
                float v00 = s[ks][0], v01 = s[ks][1], v10 = s[ks][2], v11 = s[ks][3];
                float t00 = __shfl_sync(0xffffffffu, v00, srcA);
                float t01 = __shfl_sync(0xffffffffu, v01, srcA);
                float t02 = __shfl_sync(0xffffffffu, v00, srcB);
                float t03 = __shfl_sync(0xffffffffu, v01, srcB);
                float u00 = __shfl_sync(0xffffffffu, v10, srcA);
                float u01 = __shfl_sync(0xffffffffu, v11, srcA);
                float u02 = __shfl_sync(0xffffffffu, v10, srcB);
                float u03 = __shfl_sync(0xffffffffu, v11, srcB);
                uint32_t a[4];
                a[0] = f2tf((c & 1) ? t01 : t00);
                a[1] = f2tf((c & 1) ? u01 : u00);
                a[2] = f2tf((c & 1) ? t03 : t02);
                a[3] = f2tf((c & 1) ? u03 : u02);
                #pragma unroll
                for (int nt = 0; nt < 16; nt++) {
                    uint32_t b0 = Vs[8*ks + c    ][nt*8 + g];
                    uint32_t b1 = Vs[8*ks + c + 4][nt*8 + g];
                    mma8(o[nt], a, b0, b1);
                }
            }
        }
    }

    // epilogue
    int token0 = b * SS + r0;
    int token1 = b * SS + r1;
    float w0 = g_hw[token0 * KK + kslot] / l0;
    float w1 = g_hw[token1 * KK + kslot] / l1;
    size_t base0 = ((size_t)token0 * KK + kslot) * DD;
    size_t base1 = ((size_t)token1 * KK + kslot) * DD;
    uint32_t* go = (uint32_t*)g_o;
    #pragma unroll
    for (int nt = 0; nt < 16; nt++) {
        int col = nt * 8 + 2 * c;
        uint2 v0 = { f2tf(o[nt][0] * w0), f2tf(o[nt][1] * w0) };
        uint2 v1 = { f2tf(o[nt][2] * w1), f2tf(o[nt][3] * w1) };
        *(uint2*)&go[base0 + col] = v0;
        *(uint2*)&go[base1 + col] = v1;
    }
}

// ---------------- kernel 5: output projection, double-buffered ----------------
#define OUT_SMEM (4 * 32 * 136 * 4)
__global__ __launch_bounds__(256) void outproj_mma_kernel(const float* __restrict__ Wo,
                                                          float* __restrict__ out) {
    const int rbase = blockIdx.x * 128;
    const int cbase = blockIdx.y * 128;

    extern __shared__ uint32_t osm[];
    uint32_t (*Xb[2])[136] = { (uint32_t(*)[136])osm,
                               (uint32_t(*)[136])(osm + 4352) };
    uint32_t (*Wb[2])[136] = { (uint32_t(*)[136])(osm + 8704),
                               (uint32_t(*)[136])(osm + 13056) };

    const int tid = threadIdx.x;
    const int lane = tid & 31, warp = tid >> 5;
    const int g = lane >> 2, c = lane & 3;
    const int wr = (warp >> 1) * 32;
    const int wc = (warp & 1) * 64;

    const int myrow = tid >> 1;
    const int koff = (tid & 1) * 16;
    const uint32_t* arow = (const uint32_t*)g_o + (size_t)(rbase + myrow) * EE + koff;

    float acc[2][8][4];
    #pragma unroll
    for (int mt = 0; mt < 2; mt++)
        #pragma unroll
        for (int nt = 0; nt < 8; nt++)
            #pragma unroll
            for (int q = 0; q < 4; q++) acc[mt][nt][q] = 0.f;

    uint4  px[4];
    float4 pw[4];
    #pragma unroll
    for (int j = 0; j < 4; j++) px[j] = *(const uint4*)(arow + 4 * j);
    #pragma unroll
    for (int r = 0; r < 4; r++) {
        int i = tid + 256 * r;
        int k = i >> 5, n4 = (i & 31) * 4;
        pw[r] = *(const float4*)(Wo + (size_t)k * EE + cbase + n4);
    }
    {
        uint32_t (*Xs)[136] = Xb[0];
        uint32_t (*Ws)[136] = Wb[0];
        #pragma unroll
        for (int j = 0; j < 4; j++) {
            Xs[koff + 4*j + 0][myrow] = px[j].x;
            Xs[koff + 4*j + 1][myrow] = px[j].y;
            Xs[koff + 4*j + 2][myrow] = px[j].z;
            Xs[koff + 4*j + 3][myrow] = px[j].w;
        }
        #pragma unroll
        for (int r = 0; r < 4; r++) {
            int i = tid + 256 * r;
            int k = i >> 5, n4 = (i & 31) * 4;
            uint4 u = { f2tf(pw[r].x), f2tf(pw[r].y), f2tf(pw[r].z), f2tf(pw[r].w) };
            *(uint4*)&Ws[k][n4] = u;
        }
    }
    __syncthreads();

    for (int cch = 0; cch < 32; cch++) {
        if (cch + 1 < 32) {
            int ec = (cch + 1) * 32;
            #pragma unroll
            for (int j = 0; j < 4; j++) px[j] = *(const uint4*)(arow + ec + 4 * j);
            #pragma unroll
            for (int r = 0; r < 4; r++) {
                int i = tid + 256 * r;
                int k = i >> 5, n4 = (i & 31) * 4;
                pw[r] = *(const float4*)(Wo + (size_t)(ec + k) * EE + cbase + n4);
            }
        }
        {
            uint32_t (*Xs)[136] = Xb[cch & 1];
            uint32_t (*Ws)[136] = Wb[cch & 1];
            #pragma unroll
            for (int ks = 0; ks < 4; ks++) {
                uint32_t a[2][4];
                #pragma unroll
                for (int mt = 0; mt < 2; mt++) {
                    int row = wr + mt * 16;
                    a[mt][0] = Xs[ks*8 + c    ][row + g];
                    a[mt][1] = Xs[ks*8 + c    ][row + g + 8];
                    a[mt][2] = Xs[ks*8 + c + 4][row + g];
                    a[mt][3] = Xs[ks*8 + c + 4][row + g + 8];
                }
                #pragma unroll
                for (int nt = 0; nt < 8; nt++) {
                    uint32_t b0 = Ws[ks*8 + c    ][wc + nt*8 + g];
                    uint32_t b1 = Ws[ks*8 + c + 4][wc + nt*8 + g];
                    mma8(acc[0][nt], a[0], b0, b1);
                    mma8(acc[1][nt], a[1], b0, b1);
                }
            }
        }
        if (cch + 1 < 32) {
            uint32_t (*Xs)[136] = Xb[(cch + 1) & 1];
            uint32_t (*Ws)[136] = Wb[(cch + 1) & 1];
            #pragma unroll
            for (int j = 0; j < 4; j++) {
                Xs[koff + 4*j + 0][myrow] = px[j].x;
                Xs[koff + 4*j + 1][myrow] = px[j].y;
                Xs[koff + 4*j + 2][myrow] = px[j].z;
                Xs[koff + 4*j + 3][myrow] = px[j].w;
            }
            #pragma unroll
            for (int r = 0; r < 4; r++) {
                int i = tid + 256 * r;
                int k = i >> 5, n4 = (i & 31) * 4;
                uint4 u = { f2tf(pw[r].x), f2tf(pw[r].y), f2tf(pw[r].z), f2tf(pw[r].w) };
                *(uint4*)&Ws[k][n4] = u;
            }
        }
        __syncthreads();
    }

    #pragma unroll
    for (int mt = 0; mt < 2; mt++) {
        size_t row0 = rbase + wr + mt * 16 + g;
        size_t row1 = row0 + 8;
        #pragma unroll
        for (int nt = 0; nt < 8; nt++) {
            int col = cbase + wc + nt * 8 + 2 * c;
            float2 v0 = { acc[mt][nt][0], acc[mt][nt][1] };
            float2 v1 = { acc[mt][nt][2], acc[mt][nt][3] };
            *(float2*)&out[row0 * EE + col] = v0;
            *(float2*)&out[row1 * EE + col] = v1;
        }
    }
}

// ---------------- kernel 6: finalize (parallel) ----------------
__global__ __launch_bounds__(512) void finalize_kernel(float* __restrict__ out, int out_size) {
    __shared__ float s_bal[BB * HH];
    __shared__ float s_ent[512];
    const int tid = threadIdx.x;

    // balance: 64 (b,h) pairs x 8 threads each
    {
        int pair = tid >> 3, sub = tid & 7;
        int b = pair >> 5, h = pair & 31;
        float psum = 0.f, fcnt = 0.f;
        for (int s = sub; s < SS; s += 8) {
            int t = b * SS + s;
            psum += g_probs[(size_t)t * HH + h];
            fcnt += (g_primary[t] == h) ? 1.f : 0.f;
        }
        #pragma unroll
        for (int off = 4; off; off >>= 1) {
            psum += __shfl_xor_sync(0xffffffffu, psum, off);
            fcnt += __shfl_xor_sync(0xffffffffu, fcnt, off);
        }
        if (sub == 0) s_bal[pair] = (fcnt / SS) * (psum / SS);
    }
    // entropy
    {
        float e = 0.f;
        for (int i = tid; i < BSZ; i += 512) e += g_ent[i];
        s_ent[tid] = e;
    }
    __syncthreads();
    for (int h = 256; h >= 1; h >>= 1) {
        if (tid < h) s_ent[tid] += s_ent[tid + h];
        __syncthreads();
    }
    const int base = BSZ * EE;
    if (tid == 0 && out_size > base) {
        float bal = 0.f;
        for (int i = 0; i < BB * HH; i++) bal += s_bal[i];
        bal = (float)HH * (bal / BB);
        float ent = s_ent[0] / (float)BSZ;
        out[out_size - 1] = bal - 0.01f * ent;
    }
    if (out_size > base) {
        for (int i = base + tid; i < out_size - 1; i += 512) out[i] = 0.f;
    }
}

// ---------------- launcher ----------------
extern "C" void kernel_launch(void* const* d_in, const int* in_sizes, int n_in,
                              void* d_out, int out_size) {
    const float* x  = (const float*)d_in[0];
    const float* Wq = (const float*)d_in[1];
    const float* Wk = (const float*)d_in[2];
    const float* Wv = (const float*)d_in[3];
    const float* Wr = (const float*)d_in[4];
    const float* Wo = (const float*)d_in[5];
    for (int i = 0; i < n_in; i++) {
        if (in_sizes[i] == EE * HH)      Wr = (const float*)d_in[i];
        if (in_sizes[i] == KK * DD * EE) Wo = (const float*)d_in[i];
    }
    float* out = (float*)d_out;

    static int attr_set = 0;
    if (!attr_set) {
        cudaFuncSetAttribute(attn_mma_kernel,
                             cudaFuncAttributeMaxDynamicSharedMemorySize, ATTN_SMEM);
        cudaFuncSetAttribute(proj_mma_kernel,
                             cudaFuncAttributeMaxDynamicSharedMemorySize, PROJ_SMEM);
        cudaFuncSetAttribute(outproj_mma_kernel,
                             cudaFuncAttributeMaxDynamicSharedMemorySize, OUT_SMEM);
        attr_set = 1;
    }

    zero_kernel<<<1, 32>>>();
    router_kernel<<<BSZ, 256>>>(x, Wr);
    proj_mma_kernel<<<dim3(32, HH, 3), 256, PROJ_SMEM>>>(x, Wq, Wk, Wv);
    rope_kernel<<<(BKH * SS * (DD / 2) + 255) / 256, 256>>>();
    attn_mma_kernel<<<dim3(BKH, SS / 128), 256, ATTN_SMEM>>>();
    outproj_mma_kernel<<<dim3(BSZ / 128, EE / 128), 256, OUT_SMEM>>>(Wo, out);
    finalize_kernel<<<1, 512>>>(out, out_size);
}

// round 8
// speedup vs baseline: 5.0397x; 1.5917x over previous
#include <cuda_runtime.h>
#include <cuda_fp16.h>
#include <math.h>
#include <stdint.h>

#define BB 2
#define SS 2048
#define EE 1024
#define HH 32
#define KK 8
#define DD 128
#define BSZ (BB*SS)     // 4096 tokens
#define BKH (BB*KK)     // 16 head-slots

// ---------------- scratch ----------------
static __device__ float  g_hw[BSZ*KK];
static __device__ float  g_probs[BSZ*HH];
static __device__ float  g_ent[BSZ];
static __device__ int    g_primary[BSZ];
static __device__ int    g_bcnt[HH];
static __device__ int    g_bucket[HH*BSZ];
static __device__ __half g_xh[(size_t)BSZ*EE];          // x in fp16
static __device__ __half g_wqt[(size_t)HH*DD*EE];       // Wq^T fp16 [n][k]
static __device__ __half g_wkt[(size_t)HH*DD*EE];
static __device__ __half g_wvt[(size_t)HH*DD*EE];
static __device__ __half g_wot[(size_t)EE*KK*DD];       // Wo^T fp16 [n=E][k=K*D]
static __device__ float  g_qf[(size_t)BKH*SS*DD];       // q fp32 (pre-rope)
static __device__ float  g_kf[(size_t)BKH*SS*DD];
static __device__ __half g_qh[(size_t)BKH*SS*DD];       // post-rope fp16, scaled by (1/sqrt(D))*log2e
static __device__ __half g_kh[(size_t)BKH*SS*DD];
static __device__ __half g_vh[(size_t)BKH*SS*DD];
static __device__ __half g_oh[(size_t)BSZ*KK*DD];       // attn output fp16

// ---------------- helpers ----------------
__device__ __forceinline__ float fexp2(float x) {
    float y;
    asm("ex2.approx.f32 %0, %1;" : "=f"(y) : "f"(x));
    return y;
}
__device__ __forceinline__ void mma16(float* cc, const uint32_t* a, uint32_t b0, uint32_t b1) {
    asm volatile(
        "mma.sync.aligned.m16n8k16.row.col.f32.f16.f16.f32 "
        "{%0,%1,%2,%3},{%4,%5,%6,%7},{%8,%9},{%0,%1,%2,%3};\n"
        : "+f"(cc[0]), "+f"(cc[1]), "+f"(cc[2]), "+f"(cc[3])
        : "r"(a[0]), "r"(a[1]), "r"(a[2]), "r"(a[3]), "r"(b0), "r"(b1));
}
__device__ __forceinline__ void ldsm4t(uint32_t& r0, uint32_t& r1, uint32_t& r2, uint32_t& r3,
                                       uint32_t addr) {
    asm volatile("ldmatrix.sync.aligned.m8n8.x4.trans.shared.b16 {%0,%1,%2,%3}, [%4];"
                 : "=r"(r0), "=r"(r1), "=r"(r2), "=r"(r3) : "r"(addr));
}
__device__ __forceinline__ uint32_t pack2(float a, float b) {
    __half2 h = __floats2half2_rn(a, b);
    return *(uint32_t*)&h;
}
__device__ __forceinline__ void cp16(void* smem, const void* gmem) {
    uint32_t a = (uint32_t)__cvta_generic_to_shared(smem);
    asm volatile("cp.async.cg.shared.global [%0], [%1], 16;\n" :: "r"(a), "l"(gmem));
}
__device__ __forceinline__ void cp_commit() { asm volatile("cp.async.commit_group;\n"); }
template<int N> __device__ __forceinline__ void cp_wait() {
    asm volatile("cp.async.wait_group %0;\n" :: "n"(N));
}

// ---------------- kernel 0 ----------------
__global__ void zero_kernel() {
    if (threadIdx.x < HH) g_bcnt[threadIdx.x] = 0;
}

// ---------------- prep: x -> fp16 ----------------
__global__ __launch_bounds__(256) void convx_kernel(const float* __restrict__ x) {
    int i = (blockIdx.x * 256 + threadIdx.x) * 4;
    float4 v = *(const float4*)(x + i);
    __half2* d = (__half2*)(g_xh + i);
    d[0] = __floats2half2_rn(v.x, v.y);
    d[1] = __floats2half2_rn(v.z, v.w);
}

// ---------------- prep: W transpose -> fp16 [n][k] ----------------
// z 0..2 : Wq/Wk/Wv (1024 x 4096), z=3 : Wo (1024 x 1024)
__global__ __launch_bounds__(256) void transpose_kernel(const float* __restrict__ Wq,
                                                        const float* __restrict__ Wk,
                                                        const float* __restrict__ Wv,
                                                        const float* __restrict__ Wo) {
    const int z = blockIdx.z;
    const float* src = (z == 0) ? Wq : (z == 1) ? Wk : (z == 2) ? Wv : Wo;
    __half* dst = (z == 0) ? g_wqt : (z == 1) ? g_wkt : (z == 2) ? g_wvt : g_wot;
    const int C = (z < 3) ? (HH * DD) : EE;   // src cols (n)
    const int R = EE;                          // src rows (k)
    const int c0 = blockIdx.x * 32, r0 = blockIdx.y * 32;
    if (c0 >= C) return;
    __shared__ float t[32][33];
    const int tx = threadIdx.x & 31, ty = threadIdx.x >> 5;
    #pragma unroll
    for (int i = 0; i < 4; i++)
        t[ty + 8 * i][tx] = src[(size_t)(r0 + ty + 8 * i) * C + c0 + tx];
    __syncthreads();
    #pragma unroll
    for (int i = 0; i < 4; i++)
        dst[(size_t)(c0 + ty + 8 * i) * R + r0 + tx] = __float2half(t[tx][ty + 8 * i]);
}

// ---------------- kernel 1: router (exact fp32) ----------------
__global__ __launch_bounds__(256) void router_kernel(const float* __restrict__ x,
                                                     const float* __restrict__ Wr) {
    const int token = blockIdx.x;
    __shared__ float xs[EE];
    __shared__ float part[8][HH];
    __shared__ float s_topv[KK];
    __shared__ int   s_topi[KK];
    const int tid = threadIdx.x;

    const float4* xv = (const float4*)(x + (size_t)token * EE);
    float4* xsv = (float4*)xs;
    for (int i = tid; i < EE/4; i += 256) xsv[i] = xv[i];
    __syncthreads();

    const int warp = tid >> 5, lane = tid & 31;
    float acc = 0.f;
    const int e0 = warp * 128;
    #pragma unroll 4
    for (int e = 0; e < 128; e++)
        acc = fmaf(xs[e0 + e], Wr[(size_t)(e0 + e) * HH + lane], acc);
    part[warp][lane] = acc;
    __syncthreads();

    if (warp == 0) {
        float logit = 0.f;
        #pragma unroll
        for (int w = 0; w < 8; w++) logit += part[w][lane];

        float m = logit;
        #pragma unroll
        for (int o = 16; o; o >>= 1) m = fmaxf(m, __shfl_xor_sync(0xffffffffu, m, o));
        float ex = expf(logit - m);
        float sum = ex;
        #pragma unroll
        for (int o = 16; o; o >>= 1) sum += __shfl_xor_sync(0xffffffffu, sum, o);
        float prob = ex / sum;
        g_probs[(size_t)token * HH + lane] = prob;
        float et = -prob * logf(prob + 1e-8f);
        #pragma unroll
        for (int o = 16; o; o >>= 1) et += __shfl_xor_sync(0xffffffffu, et, o);
        if (lane == 0) g_ent[token] = et;

        float cur = logit;
        for (int j = 0; j < KK; j++) {
            float bv = cur; int bi = lane;
            #pragma unroll
            for (int o = 16; o; o >>= 1) {
                float ov = __shfl_xor_sync(0xffffffffu, bv, o);
                int   oi = __shfl_xor_sync(0xffffffffu, bi, o);
                if (ov > bv || (ov == bv && oi < bi)) { bv = ov; bi = oi; }
            }
            if (lane == 0) { s_topv[j] = bv; s_topi[j] = bi; }
            if (lane == bi) cur = -INFINITY;
        }
        __syncwarp();

        if (lane < KK) {
            float tv = s_topv[lane];
            float e2 = expf(tv - s_topv[0]);
            float s2 = e2;
            #pragma unroll
            for (int o = 4; o; o >>= 1) s2 += __shfl_xor_sync(0x000000ffu, s2, o, 8);
            int hsel = s_topi[lane];
            g_hw[token * KK + lane] = e2 / s2;
            int pos = atomicAdd(&g_bcnt[hsel], 1);
            g_bucket[hsel * BSZ + pos] = token * KK + lane;
        }
        if (lane == 0) g_primary[token] = s_topi[0];
    }
}

// ---------------- kernel 2: bucketed gather projection, fp16 MMA + cp.async ----------------
// tile 128 tokens x 128 dims, kc=64, 16 chunks, 3-buffer cp.async pipeline, 8 warps.
#define XBUF (128 * 72)                 // halves per buffer
#define PROJ_SMEM (6 * XBUF * 2)        // X0..2 + W0..2
__global__ __launch_bounds__(256) void proj_mma_kernel() {
    const int h = blockIdx.y;
    const int cnt = g_bcnt[h];
    const int t0 = blockIdx.x * 128;
    if (t0 >= cnt) return;
    const int mat = blockIdx.z;
    const __half* Wt = (mat == 0 ? g_wqt : mat == 1 ? g_wkt : g_wvt);

    extern __shared__ __half psm[];
    __half* Xbase = psm;
    __half* Wbase = psm + 3 * XBUF;
    __shared__ int codes[128];

    const int tid = threadIdx.x;
    const int lane = tid & 31, warp = tid >> 5;
    const int g = lane >> 2, c = lane & 3;
    const int wr = (warp >> 1) * 32;
    const int wc = (warp & 1) * 64;

    if (tid < 128) {
        int ii = t0 + tid;
        codes[tid] = (ii < cnt) ? g_bucket[h * BSZ + ii] : -1;
    }
    __syncthreads();

    const int srow = tid >> 1;              // staging row 0..127
    const int soff = (tid & 1) * 32;        // halves within 64-chunk
    int mycode = codes[srow];
    const __half* xrow = g_xh + (size_t)(mycode >= 0 ? (mycode >> 3) : 0) * EE + soff;
    const __half* wrow = Wt + (size_t)(h * DD + srow) * EE + soff;

    float acc[2][8][4];
    #pragma unroll
    for (int mt = 0; mt < 2; mt++)
        #pragma unroll
        for (int nt = 0; nt < 8; nt++)
            #pragma unroll
            for (int q = 0; q < 4; q++) acc[mt][nt][q] = 0.f;

    // prologue: stage chunks 0,1
    #pragma unroll
    for (int p = 0; p < 2; p++) {
        __half* xd = Xbase + p * XBUF + srow * 72 + soff;
        __half* wd = Wbase + p * XBUF + srow * 72 + soff;
        #pragma unroll
        for (int j = 0; j < 4; j++) {
            cp16(xd + 8 * j, xrow + p * 64 + 8 * j);
            cp16(wd + 8 * j, wrow + p * 64 + 8 * j);
        }
        cp_commit();
    }

    for (int cch = 0; cch < 16; cch++) {
        if (cch < 14) cp_wait<1>(); else cp_wait<0>();
        __syncthreads();
        if (cch + 2 < 16) {
            int b = (cch + 2) % 3;
            __half* xd = Xbase + b * XBUF + srow * 72 + soff;
            __half* wd = Wbase + b * XBUF + srow * 72 + soff;
            #pragma unroll
            for (int j = 0; j < 4; j++) {
                cp16(xd + 8 * j, xrow + (cch + 2) * 64 + 8 * j);
                cp16(wd + 8 * j, wrow + (cch + 2) * 64 + 8 * j);
            }
            cp_commit();
        }
        const __half* Xs = Xbase + (cch % 3) * XBUF;
        const __half* Ws = Wbase + (cch % 3) * XBUF;
        #pragma unroll
        for (int ks = 0; ks < 4; ks++) {
            uint32_t a[2][4];
            #pragma unroll
            for (int mt = 0; mt < 2; mt++) {
                int row = wr + mt * 16;
                a[mt][0] = *(const uint32_t*)(Xs + (row + g    ) * 72 + 16*ks + 2*c);
                a[mt][1] = *(const uint32_t*)(Xs + (row + g + 8) * 72 + 16*ks + 2*c);
                a[mt][2] = *(const uint32_t*)(Xs + (row + g    ) * 72 + 16*ks + 2*c + 8);
                a[mt][3] = *(const uint32_t*)(Xs + (row + g + 8) * 72 + 16*ks + 2*c + 8);
            }
            #pragma unroll
            for (int nt = 0; nt < 8; nt++) {
                int n = wc + nt * 8 + g;
                uint32_t b0 = *(const uint32_t*)(Ws + n * 72 + 16*ks + 2*c);
                uint32_t b1 = *(const uint32_t*)(Ws + n * 72 + 16*ks + 2*c + 8);
                mma16(acc[0][nt], a[0], b0, b1);
                mma16(acc[1][nt], a[1], b0, b1);
            }
        }
        __syncthreads();
    }

    // epilogue: scatter rows by code. q/k -> fp32, v -> fp16
    #pragma unroll
    for (int mt = 0; mt < 2; mt++) {
        int r0 = wr + mt * 16 + g;
        int r1 = r0 + 8;
        int code0 = codes[r0], code1 = codes[r1];
        size_t base0 = 0, base1 = 0;
        if (code0 >= 0) {
            int token = code0 >> 3, slot = code0 & 7;
            base0 = ((size_t)(((token >> 11) * KK + slot) * SS + (token & (SS-1)))) * DD;
        }
        if (code1 >= 0) {
            int token = code1 >> 3, slot = code1 & 7;
            base1 = ((size_t)(((token >> 11) * KK + slot) * SS + (token & (SS-1)))) * DD;
        }
        #pragma unroll
        for (int nt = 0; nt < 8; nt++) {
            int col = wc + nt * 8 + 2 * c;
            if (mat == 2) {
                if (code0 >= 0)
                    *(__half2*)&g_vh[base0 + col] = __floats2half2_rn(acc[mt][nt][0], acc[mt][nt][1]);
                if (code1 >= 0)
                    *(__half2*)&g_vh[base1 + col] = __floats2half2_rn(acc[mt][nt][2], acc[mt][nt][3]);
            } else {
                float* dst = (mat == 0) ? g_qf : g_kf;
                if (code0 >= 0) { float2 v = { acc[mt][nt][0], acc[mt][nt][1] }; *(float2*)&dst[base0 + col] = v; }
                if (code1 >= 0) { float2 v = { acc[mt][nt][2], acc[mt][nt][3] }; *(float2*)&dst[base1 + col] = v; }
            }
        }
    }
}

// ---------------- kernel 3: RoPE fp32 -> fp16; q gets (1/sqrt(D))*log2e ----------------
__global__ __launch_bounds__(256) void rope_kernel() {
    int idx = blockIdx.x * blockDim.x + threadIdx.x;   // BKH*SS*32 threads
    const int total = BKH * SS * 32;
    if (idx >= total) return;
    int d2 = idx & 31;
    int rest = idx >> 5;
    int s = rest & (SS - 1);
    int d0 = 2 * d2;
    const float Cf = 9.210340371976184f / 64.f;
    float inv0 = expf(-(float)d0 * Cf);
    float inv1 = expf(-(float)(d0 + 1) * Cf);
    float sn0, cs0, sn1, cs1;
    sincosf(s * inv0, &sn0, &cs0);
    sincosf(s * inv1, &sn1, &cs1);
    const float scale = 0.12751691579231338f;  // (1/sqrt(128)) * log2(e)
    size_t i0 = ((size_t)rest << 7) + d0;
    float qa = g_qf[i0], qb = g_qf[i0+1], qc_ = g_qf[i0+64], qd = g_qf[i0+65];
    *(__half2*)&g_qh[i0]      = __floats2half2_rn((qa*cs0 - qc_*sn0)*scale, (qb*cs1 - qd*sn1)*scale);
    *(__half2*)&g_qh[i0 + 64] = __floats2half2_rn((qc_*cs0 + qa*sn0)*scale, (qd*cs1 + qb*sn1)*scale);
    float ka = g_kf[i0], kb_ = g_kf[i0+1], kc_ = g_kf[i0+64], kd = g_kf[i0+65];
    *(__half2*)&g_kh[i0]      = __floats2half2_rn(ka*cs0 - kc_*sn0, kb_*cs1 - kd*sn1);
    *(__half2*)&g_kh[i0 + 64] = __floats2half2_rn(kc_*cs0 + ka*sn0, kd*cs1 + kb_*sn1);
}

// ---------------- kernel 4: flash attention fp16, q-tile 128, 8 warps ----------------
__global__ __launch_bounds__(256, 1) void attn_mma_kernel() {
    __shared__ __half Ks[64][136];
    __shared__ __half Vs[64][136];

    const int bk = blockIdx.x;
    const int qt = gridDim.y - 1 - blockIdx.y;     // big tiles first
    const int qbase = qt * 128;
    const int b = bk >> 3, kslot = bk & 7;
    const int tid = threadIdx.x;
    const int lane = tid & 31, warp = tid >> 5;
    const int g = lane >> 2, c = lane & 3;

    const __half* Qp = g_qh + (size_t)bk * SS * DD;
    const __half* Kp = g_kh + (size_t)bk * SS * DD;
    const __half* Vp = g_vh + (size_t)bk * SS * DD;

    const int lrow = tid >> 2;            // 0..63
    const int coff = (tid & 3) * 32;      // halves: 0,32,64,96

    // stage K0
    {
        const __half* src = Kp + (size_t)lrow * DD + coff;
        #pragma unroll
        for (int j = 0; j < 4; j++) cp16(&Ks[lrow][coff + 8*j], src + 8*j);
        cp_commit();
    }

    // Q fragments from gmem (pre-scaled fp16)
    const int r0 = qbase + warp * 16 + g;
    const int r1 = r0 + 8;
    uint32_t qf[8][4];
    {
        const __half* q0 = Qp + (size_t)r0 * DD;
        const __half* q1 = Qp + (size_t)r1 * DD;
        #pragma unroll
        for (int ks = 0; ks < 8; ks++) {
            qf[ks][0] = *(const uint32_t*)(q0 + 16*ks + 2*c);
            qf[ks][1] = *(const uint32_t*)(q1 + 16*ks + 2*c);
            qf[ks][2] = *(const uint32_t*)(q0 + 16*ks + 2*c + 8);
            qf[ks][3] = *(const uint32_t*)(q1 + 16*ks + 2*c + 8);
        }
    }

    float o[16][4];
    #pragma unroll
    for (int nt = 0; nt < 16; nt++)
        #pragma unroll
        for (int q = 0; q < 4; q++) o[nt][q] = 0.f;
    float m0 = -INFINITY, m1 = -INFINITY, l0 = 0.f, l1 = 0.f;

    const uint32_t vs_base = (uint32_t)__cvta_generic_to_shared(&Vs[0][0]);
    const int nkt = 2 * qt + 2;
    const int wlast = qbase + warp * 16 + 16;

    float s[8][4];
    uint32_t pa[4][4];   // P a-frags per k16 step

    for (int kt = 0; kt < nkt; kt++) {
        const int kb = kt * 64;
        const bool act = (kb < wlast);
        cp_wait<0>();
        __syncthreads();

        // stage V_kt
        {
            const __half* src = Vp + (size_t)(kb + lrow) * DD + coff;
            #pragma unroll
            for (int j = 0; j < 4; j++) cp16(&Vs[lrow][coff + 8*j], src + 8*j);
            cp_commit();
        }

        if (act) {
            #pragma unroll
            for (int nt = 0; nt < 8; nt++)
                #pragma unroll
                for (int q = 0; q < 4; q++) s[nt][q] = 0.f;
            #pragma unroll
            for (int ks = 0; ks < 8; ks++) {
                #pragma unroll
                for (int nt = 0; nt < 8; nt++) {
                    int n = nt * 8 + g;
                    uint32_t b0 = *(const uint32_t*)(&Ks[n][16*ks + 2*c]);
                    uint32_t b1 = *(const uint32_t*)(&Ks[n][16*ks + 2*c + 8]);
                    mma16(s[nt], qf[ks], b0, b1);
                }
            }
        }
        __syncthreads();

        // stage K_{kt+1}
        if (kt + 1 < nkt) {
            const __half* src = Kp + (size_t)(kb + 64 + lrow) * DD + coff;
            #pragma unroll
            for (int j = 0; j < 4; j++) cp16(&Ks[lrow][coff + 8*j], src + 8*j);
            cp_commit();
        }

        if (act) {
            if (kb + 63 > r0) {
                #pragma unroll
                for (int nt = 0; nt < 8; nt++) {
                    int col = kb + nt * 8 + 2 * c;
                    if (col     > r0) s[nt][0] = -INFINITY;
                    if (col + 1 > r0) s[nt][1] = -INFINITY;
                    if (col     > r1) s[nt][2] = -INFINITY;
                    if (col + 1 > r1) s[nt][3] = -INFINITY;
                }
            }
            float mx0 = -INFINITY, mx1 = -INFINITY;
            #pragma unroll
            for (int nt = 0; nt < 8; nt++) {
                mx0 = fmaxf(mx0, fmaxf(s[nt][0], s[nt][1]));
                mx1 = fmaxf(mx1, fmaxf(s[nt][2], s[nt][3]));
            }
            #pragma unroll
            for (int off = 1; off <= 2; off <<= 1) {
                mx0 = fmaxf(mx0, __shfl_xor_sync(0xffffffffu, mx0, off));
                mx1 = fmaxf(mx1, __shfl_xor_sync(0xffffffffu, mx1, off));
            }
            float mn0 = fmaxf(m0, mx0), mn1 = fmaxf(m1, mx1);
            float al0 = fexp2(m0 - mn0), al1 = fexp2(m1 - mn1);
            m0 = mn0; m1 = mn1;
            float rs0 = 0.f, rs1 = 0.f;
            #pragma unroll
            for (int nt = 0; nt < 8; nt++) {
                s[nt][0] = fexp2(s[nt][0] - mn0);
                s[nt][1] = fexp2(s[nt][1] - mn0);
                s[nt][2] = fexp2(s[nt][2] - mn1);
                s[nt][3] = fexp2(s[nt][3] - mn1);
                rs0 += s[nt][0] + s[nt][1];
                rs1 += s[nt][2] + s[nt][3];
            }
            #pragma unroll
            for (int off = 1; off <= 2; off <<= 1) {
                rs0 += __shfl_xor_sync(0xffffffffu, rs0, off);
                rs1 += __shfl_xor_sync(0xffffffffu, rs1, off);
            }
            l0 = l0 * al0 + rs0;
            l1 = l1 * al1 + rs1;
            #pragma unroll
            for (int nt = 0; nt < 16; nt++) {
                o[nt][0] *= al0; o[nt][1] *= al0;
                o[nt][2] *= al1; o[nt][3] *= al1;
            }
            // P c-frags ARE fp16 a-frags: just pack
            #pragma unroll
            for (int k2 = 0; k2 < 4; k2++) {
                pa[k2][0] = pack2(s[2*k2][0],   s[2*k2][1]);
                pa[k2][1] = pack2(s[2*k2][2],   s[2*k2][3]);
                pa[k2][2] = pack2(s[2*k2+1][0], s[2*k2+1][1]);
                pa[k2][3] = pack2(s[2*k2+1][2], s[2*k2+1][3]);
            }
        }

        if (kt + 1 < nkt) cp_wait<1>(); else cp_wait<0>();
        __syncthreads();

        if (act) {
            // O += P V, V-frags via ldmatrix.trans
            #pragma unroll
            for (int k2 = 0; k2 < 4; k2++) {
                int kv0 = k2 * 16;
                #pragma unroll
                for (int ntp = 0; ntp < 8; ntp++) {
                    int row = kv0 + (lane & 15);
                    int col = ntp * 16 + (lane >> 4) * 8;
                    uint32_t addr = vs_base + (uint32_t)(row * 136 + col) * 2;
                    uint32_t r0v, r1v, r2v, r3v;
                    ldsm4t(r0v, r1v, r2v, r3v, addr);
                    mma16(o[2*ntp],     pa[k2], r0v, r1v);
                    mma16(o[2*ntp + 1], pa[k2], r2v, r3v);
                }
            }
        }
    }

    // epilogue: normalize, weight, store fp16
    int token0 = b * SS + r0;
    int token1 = b * SS + r1;
    float w0 = g_hw[token0 * KK + kslot] / l0;
    float w1 = g_hw[token1 * KK + kslot] / l1;
    size_t base0 = ((size_t)token0 * KK + kslot) * DD;
    size_t base1 = ((size_t)token1 * KK + kslot) * DD;
    #pragma unroll
    for (int nt = 0; nt < 16; nt++) {
        int col = nt * 8 + 2 * c;
        *(__half2*)&g_oh[base0 + col] = __floats2half2_rn(o[nt][0] * w0, o[nt][1] * w0);
        *(__half2*)&g_oh[base1 + col] = __floats2half2_rn(o[nt][2] * w1, o[nt][3] * w1);
    }
}

// ---------------- kernel 5: output projection fp16 ----------------
#define OUT_SMEM (6 * XBUF * 2)
__global__ __launch_bounds__(256) void outproj_mma_kernel(float* __restrict__ out) {
    const int rbase = blockIdx.x * 128;
    const int cbase = blockIdx.y * 128;

    extern __shared__ __half osm[];
    __half* Xbase = osm;
    __half* Wbase = osm + 3 * XBUF;

    const int tid = threadIdx.x;
    const int lane = tid & 31, warp = tid >> 5;
    const int g = lane >> 2, c = lane & 3;
    const int wr = (warp >> 1) * 32;
    const int wc = (warp & 1) * 64;

    const int srow = tid >> 1;
    const int soff = (tid & 1) * 32;
    const __half* arow = g_oh + (size_t)(rbase + srow) * EE + soff;
    const __half* wrow = g_wot + (size_t)(cbase + srow) * (KK * DD) + soff;

    float acc[2][8][4];
    #pragma unroll
    for (int mt = 0; mt < 2; mt++)
        #pragma unroll
        for (int nt = 0; nt < 8; nt++)
            #pragma unroll
            for (int q = 0; q < 4; q++) acc[mt][nt][q] = 0.f;

    #pragma unroll
    for (int p = 0; p < 2; p++) {
        __half* xd = Xbase + p * XBUF + srow * 72 + soff;
        __half* wd = Wbase + p * XBUF + srow * 72 + soff;
        #pragma unroll
        for (int j = 0; j < 4; j++) {
            cp16(xd + 8 * j, arow + p * 64 + 8 * j);
            cp16(wd + 8 * j, wrow + p * 64 + 8 * j);
        }
        cp_commit();
    }

    for (int cch = 0; cch < 16; cch++) {
        if (cch < 14) cp_wait<1>(); else cp_wait<0>();
        __syncthreads();
        if (cch + 2 < 16) {
            int bq = (cch + 2) % 3;
            __half* xd = Xbase + bq * XBUF + srow * 72 + soff;
            __half* wd = Wbase + bq * XBUF + srow * 72 + soff;
            #pragma unroll
            for (int j = 0; j < 4; j++) {
                cp16(xd + 8 * j, arow + (cch + 2) * 64 + 8 * j);
                cp16(wd + 8 * j, wrow + (cch + 2) * 64 + 8 * j);
            }
            cp_commit();
        }
        const __half* Xs = Xbase + (cch % 3) * XBUF;
        const __half* Ws = Wbase + (cch % 3) * XBUF;
        #pragma unroll
        for (int ks = 0; ks < 4; ks++) {
            uint32_t a[2][4];
            #pragma unroll
            for (int mt = 0; mt < 2; mt++) {
                int row = wr + mt * 16;
                a[mt][0] = *(const uint32_t*)(Xs + (row + g    ) * 72 + 16*ks + 2*c);
                a[mt][1] = *(const uint32_t*)(Xs + (row + g + 8) * 72 + 16*ks + 2*c);
                a[mt][2] = *(const uint32_t*)(Xs + (row + g    ) * 72 + 16*ks + 2*c + 8);
                a[mt][3] = *(const uint32_t*)(Xs + (row + g + 8) * 72 + 16*ks + 2*c + 8);
            }
            #pragma unroll
            for (int nt = 0; nt < 8; nt++) {
                int n = wc + nt * 8 + g;
                uint32_t b0 = *(const uint32_t*)(Ws + n * 72 + 16*ks + 2*c);
                uint32_t b1 = *(const uint32_t*)(Ws + n * 72 + 16*ks + 2*c + 8);
                mma16(acc[0][nt], a[0], b0, b1);
                mma16(acc[1][nt], a[1], b0, b1);
            }
        }
        __syncthreads();
    }

    #pragma unroll
    for (int mt = 0; mt < 2; mt++) {
        size_t row0 = rbase + wr + mt * 16 + g;
        size_t row1 = row0 + 8;
        #pragma unroll
        for (int nt = 0; nt < 8; nt++) {
            int col = cbase + wc + nt * 8 + 2 * c;
            float2 v0 = { acc[mt][nt][0], acc[mt][nt][1] };
            float2 v1 = { acc[mt][nt][2], acc[mt][nt][3] };
            *(float2*)&out[row0 * EE + col] = v0;
            *(float2*)&out[row1 * EE + col] = v1;
        }
    }
}

// ---------------- kernel 6: finalize (parallel) ----------------
__global__ __launch_bounds__(512) void finalize_kernel(float* __restrict__ out, int out_size) {
    __shared__ float s_bal[BB * HH];
    __shared__ float s_ent[512];
    const int tid = threadIdx.x;
    {
        int pair = tid >> 3, sub = tid & 7;
        int b = pair >> 5, h = pair & 31;
        float psum = 0.f, fcnt = 0.f;
        for (int s = sub; s < SS; s += 8) {
            int t = b * SS + s;
            psum += g_probs[(size_t)t * HH + h];
            fcnt += (g_primary[t] == h) ? 1.f : 0.f;
        }
        #pragma unroll
        for (int off = 4; off; off >>= 1) {
            psum += __shfl_xor_sync(0xffffffffu, psum, off);
            fcnt += __shfl_xor_sync(0xffffffffu, fcnt, off);
        }
        if (sub == 0) s_bal[pair] = (fcnt / SS) * (psum / SS);
    }
    {
        float e = 0.f;
        for (int i = tid; i < BSZ; i += 512) e += g_ent[i];
        s_ent[tid] = e;
    }
    __syncthreads();
    for (int h = 256; h >= 1; h >>= 1) {
        if (tid < h) s_ent[tid] += s_ent[tid + h];
        __syncthreads();
    }
    const int base = BSZ * EE;
    if (tid == 0 && out_size > base) {
        float bal = 0.f;
        for (int i = 0; i < BB * HH; i++) bal += s_bal[i];
        bal = (float)HH * (bal / BB);
        float ent = s_ent[0] / (float)BSZ;
        out[out_size - 1] = bal - 0.01f * ent;
    }
    if (out_size > base) {
        for (int i = base + tid; i < out_size - 1; i += 512) out[i] = 0.f;
    }
}

// ---------------- launcher ----------------
extern "C" void kernel_launch(void* const* d_in, const int* in_sizes, int n_in,
                              void* d_out, int out_size) {
    const float* x  = (const float*)d_in[0];
    const float* Wq = (const float*)d_in[1];
    const float* Wk = (const float*)d_in[2];
    const float* Wv = (const float*)d_in[3];
    const float* Wr = (const float*)d_in[4];
    const float* Wo = (const float*)d_in[5];
    for (int i = 0; i < n_in; i++) {
        if (in_sizes[i] == EE * HH)      Wr = (const float*)d_in[i];
        if (in_sizes[i] == KK * DD * EE) Wo = (const float*)d_in[i];
    }
    float* out = (float*)d_out;

    static int attr_set = 0;
    if (!attr_set) {
        cudaFuncSetAttribute(proj_mma_kernel,
                             cudaFuncAttributeMaxDynamicSharedMemorySize, PROJ_SMEM);
        cudaFuncSetAttribute(outproj_mma_kernel,
                             cudaFuncAttributeMaxDynamicSharedMemorySize, OUT_SMEM);
        attr_set = 1;
    }

    zero_kernel<<<1, 32>>>();
    convx_kernel<<<BSZ * EE / 1024, 256>>>(x);
    transpose_kernel<<<dim3((HH * DD) / 32, EE / 32, 4), 256>>>(Wq, Wk, Wv, Wo);
    router_kernel<<<BSZ, 256>>>(x, Wr);
    proj_mma_kernel<<<dim3(32, HH, 3), 256, PROJ_SMEM>>>();
    rope_kernel<<<BKH * SS * 32 / 256, 256>>>();
    attn_mma_kernel<<<dim3(BKH, SS / 128), 256>>>();
    outproj_mma_kernel<<<dim3(BSZ / 128, EE / 128), 256, OUT_SMEM>>>(out);
    finalize_kernel<<<1, 512>>>(out, out_size);
}